// round 10
// baseline (speedup 1.0000x reference)
#include <cuda_runtime.h>
#include <cuda_bf16.h>
#include <cstdint>
#include <cstddef>

// Problem constants
#define BATCH 2
#define SEQ   2048
#define EMB   1024
#define HEADS 16
#define HDIM  64
#define NTOK  (BATCH * SEQ)          // 4096
#define KDIM  (EMB * 8)              // 8192 expanded features
#define NB    7                      // spline bases per feature

// ---------------- scratch (static device globals; no allocation) ------------
// per-projection phi / W buffers (all 3 projections live simultaneously)
__device__ uint4 g_phiH4[(size_t)3 * NTOK * KDIM / 8];   // 201 MB  bf16 hi
__device__ uint4 g_phiL4[(size_t)3 * NTOK * KDIM / 8];   // 201 MB  bf16 lo
__device__ uint4 g_WH4[(size_t)3 * EMB * KDIM / 8];      // 50 MB
__device__ uint4 g_WL4[(size_t)3 * EMB * KDIM / 8];      // 50 MB
// projected Q,K,V as bf16 hi/lo split, layout [3][NTOK][EMB]
__device__ __nv_bfloat16 g_qkvH[(size_t)3 * NTOK * EMB];  // 25 MB
__device__ __nv_bfloat16 g_qkvL[(size_t)3 * NTOK * EMB];  // 25 MB

struct Ptr3 { const float* p[3]; };
struct PtrW { const float* base[3]; const float* spline[3]; const float* scaler[3]; };

// =====================  PTX helpers (compute_103-safe) ======================
__device__ __forceinline__ uint32_t smem_to_u32(const void* p) {
    uint32_t a;
    asm("{ .reg .u64 t; cvta.to.shared.u64 t, %1; cvt.u32.u64 %0, t; }" : "=r"(a) : "l"(p));
    return a;
}
__device__ __forceinline__ void cp_async16(uint32_t dst, const void* src) {
    asm volatile("cp.async.cg.shared.global [%0], [%1], 16;" :: "r"(dst), "l"(src));
}
#define CP_COMMIT() asm volatile("cp.async.commit_group;" ::: "memory")
#define CP_WAIT1()  asm volatile("cp.async.wait_group 1;" ::: "memory")
#define CP_WAIT0()  asm volatile("cp.async.wait_group 0;" ::: "memory")

__device__ __forceinline__ void ldmatrix_x4(uint32_t& r0, uint32_t& r1,
                                            uint32_t& r2, uint32_t& r3, uint32_t addr) {
    asm volatile("ldmatrix.sync.aligned.m8n8.x4.shared.b16 {%0,%1,%2,%3}, [%4];"
                 : "=r"(r0), "=r"(r1), "=r"(r2), "=r"(r3) : "r"(addr));
}
__device__ __forceinline__ void ldmatrix_x4_trans(uint32_t& r0, uint32_t& r1,
                                                  uint32_t& r2, uint32_t& r3, uint32_t addr) {
    asm volatile("ldmatrix.sync.aligned.m8n8.x4.trans.shared.b16 {%0,%1,%2,%3}, [%4];"
                 : "=r"(r0), "=r"(r1), "=r"(r2), "=r"(r3) : "r"(addr));
}
// D (fp32) += A(bf16, row) @ B(bf16, col) ; m16n8k16
__device__ __forceinline__ void mma_16816(float* d, const uint32_t* a, const uint32_t* b) {
    asm volatile(
        "mma.sync.aligned.m16n8k16.row.col.f32.bf16.bf16.f32 "
        "{%0,%1,%2,%3}, {%4,%5,%6,%7}, {%8,%9}, {%0,%1,%2,%3};"
        : "+f"(d[0]), "+f"(d[1]), "+f"(d[2]), "+f"(d[3])
        : "r"(a[0]), "r"(a[1]), "r"(a[2]), "r"(a[3]), "r"(b[0]), "r"(b[1]));
}
__device__ __forceinline__ void split_bf16(float v, __nv_bfloat16& h, __nv_bfloat16& l) {
    h = __float2bfloat16(v);
    l = __float2bfloat16(v - __bfloat162float(h));
}

// ---------------------------------------------------------------------------
// Kernel 1: expand X[NTOK, EMB] -> phi (x, B0..B6) bf16 hi/lo, [proj][NTOK, KDIM]
// grid (NTOK*EMB/256, 3)
// ---------------------------------------------------------------------------
__global__ __launch_bounds__(256) void phi_split_all(Ptr3 X) {
    int proj = blockIdx.y;
    int idx = blockIdx.x * blockDim.x + threadIdx.x;
    float x = X.p[proj][idx];

    float b[10];
#pragma unroll
    for (int t = 0; t < 10; t++) {
        float gt = -2.5f + 0.5f * (float)t;
        b[t] = (x >= gt && x < gt + 0.5f) ? 1.0f : 0.0f;
    }
#pragma unroll
    for (int p = 1; p <= 3; p++) {
#pragma unroll
        for (int t = 0; t < 10; t++) {
            if (t + p < 10) {
                float gt   = -2.5f + 0.5f * (float)t;
                float gtp  = gt + 0.5f * (float)p;
                float gtp1 = gtp + 0.5f;
                float gt1  = gt + 0.5f;
                float left  = (x - gt)   / (gtp - gt);
                float right = (gtp1 - x) / (gtp1 - gt1);
                b[t] = left * b[t] + right * b[t + 1];
            }
        }
    }
    float v[8] = {x, b[0], b[1], b[2], b[3], b[4], b[5], b[6]};
    __nv_bfloat16 hi[8], lo[8];
#pragma unroll
    for (int j = 0; j < 8; j++) split_bf16(v[j], hi[j], lo[j]);
    size_t o = (size_t)proj * (NTOK * (KDIM / 8)) + idx;
    g_phiH4[o] = *(uint4*)hi;
    g_phiL4[o] = *(uint4*)lo;
}

// ---------------------------------------------------------------------------
// Kernel 2: combined weight W[proj][EMB(out m), KDIM] row-major, bf16 hi/lo
// grid (EMB*EMB/256, 3)
// ---------------------------------------------------------------------------
__global__ __launch_bounds__(256) void wprep_split_all(PtrW Wp) {
    int proj = blockIdx.y;
    int idx = blockIdx.x * blockDim.x + threadIdx.x;
    int i = idx & (EMB - 1);
    int m = idx >> 10;
    size_t mi = (size_t)m * EMB + i;
    float v[8];
    v[0] = Wp.base[proj][mi];
    float sc = Wp.scaler[proj][mi];
    const float* sp = Wp.spline[proj] + mi * NB;
#pragma unroll
    for (int j = 0; j < NB; j++) v[1 + j] = sp[j] * sc;

    __nv_bfloat16 hi[8], lo[8];
#pragma unroll
    for (int j = 0; j < 8; j++) split_bf16(v[j], hi[j], lo[j]);
    size_t o = (size_t)proj * (EMB * (KDIM / 8)) + (size_t)m * (KDIM / 8) + i;
    g_WH4[o] = *(uint4*)hi;
    g_WL4[o] = *(uint4*)lo;
}

// ---------------------------------------------------------------------------
// Kernel 3: mma.sync GEMM  C = phi @ W^T, 3-term bf16 split.
// CTA tile 128x128x32, 8 warps (2x4), warp tile 64x32.
// 2-stage cp.async, 40KB/stage -> 2 CTAs/SM (4 warps/SMSP latency hiding).
// One launch for all 3 projections: grid (8, 32, 3).
// ---------------------------------------------------------------------------
#define BM 128
#define BN 128
#define BK 32
#define NCH (KDIM / BK)                 // 256
#define ROWB 80
#define OPTILE (128 * ROWB)             // 10240
#define OFF_AH 0
#define OFF_AL OPTILE
#define OFF_BH (2 * OPTILE)
#define OFF_BL (3 * OPTILE)
#define STAGE (4 * OPTILE)              // 40960
#define GEMM_SMEM (2 * STAGE)           // 81920

__device__ __forceinline__ void load_stage(uint32_t sbase, int k0,
                                           const __nv_bfloat16* pAh, const __nv_bfloat16* pAl,
                                           const __nv_bfloat16* pBh, const __nv_bfloat16* pBl) {
    int t = threadIdx.x;
    const __nv_bfloat16* bases[4] = {pAh, pAl, pBh, pBl};
#pragma unroll
    for (int j = 0; j < 8; j++) {
        int idx = j * 256 + t;          // 0..2047
        int op = idx >> 9;              // constant per j-pair after unroll
        int lq = idx & 511;
        int r = lq >> 2, c = lq & 3;
        cp_async16(sbase + op * OPTILE + r * ROWB + c * 16,
                   bases[op] + (size_t)r * KDIM + k0 + c * 8);
    }
}

__global__ __launch_bounds__(256, 2) void gemm_kan_mma() {
    extern __shared__ char smem[];
    uint32_t sb = smem_to_u32(smem);
    int t = threadIdx.x;
    int lane = t & 31;
    int w = t >> 5;
    int wm = w >> 2;          // 0..1 : 64 m-rows
    int wn = w & 3;           // 0..3 : 32 n-cols

    int which = blockIdx.z;
    int row0 = blockIdx.y * BM;
    int col0 = blockIdx.x * BN;
    const __nv_bfloat16* pAh = (const __nv_bfloat16*)g_phiH4 +
        (size_t)which * NTOK * KDIM + (size_t)row0 * KDIM;
    const __nv_bfloat16* pAl = (const __nv_bfloat16*)g_phiL4 +
        (size_t)which * NTOK * KDIM + (size_t)row0 * KDIM;
    const __nv_bfloat16* pBh = (const __nv_bfloat16*)g_WH4 +
        (size_t)which * EMB * KDIM + (size_t)col0 * KDIM;
    const __nv_bfloat16* pBl = (const __nv_bfloat16*)g_WL4 +
        (size_t)which * EMB * KDIM + (size_t)col0 * KDIM;

    load_stage(sb + 0 * STAGE, 0 * BK, pAh, pAl, pBh, pBl); CP_COMMIT();
    load_stage(sb + 1 * STAGE, 1 * BK, pAh, pAl, pBh, pBl); CP_COMMIT();

    float acc[4][4][4];
#pragma unroll
    for (int i = 0; i < 4; i++)
#pragma unroll
        for (int j = 0; j < 4; j++)
#pragma unroll
            for (int q = 0; q < 4; q++) acc[i][j][q] = 0.0f;

    int lr = lane & 15;
    int lh = lane >> 4;
    uint32_t a_off = (uint32_t)((wm * 64 + lr) * ROWB + lh * 16);
    uint32_t b_off = (uint32_t)((wn * 32 + lr) * ROWB + lh * 16);

    for (int c = 0; c < NCH; c++) {
        uint32_t st = sb + (c & 1) * STAGE;
        CP_WAIT1();
        __syncthreads();

#pragma unroll
        for (int ks = 0; ks < 2; ks++) {
            uint32_t koff = ks * 32;
            uint32_t ah[4][4];
#pragma unroll
            for (int i = 0; i < 4; i++)
                ldmatrix_x4(ah[i][0], ah[i][1], ah[i][2], ah[i][3],
                            st + OFF_AH + a_off + i * 16 * ROWB + koff);
            uint32_t bh[2][4];
#pragma unroll
            for (int p = 0; p < 2; p++)
                ldmatrix_x4(bh[p][0], bh[p][1], bh[p][2], bh[p][3],
                            st + OFF_BH + b_off + p * 16 * ROWB + koff);
            // pass 1: Ah * Bh
#pragma unroll
            for (int i = 0; i < 4; i++)
#pragma unroll
                for (int p = 0; p < 2; p++) {
                    uint32_t b0[2] = {bh[p][0], bh[p][2]};
                    uint32_t b1[2] = {bh[p][1], bh[p][3]};
                    mma_16816(acc[i][p * 2 + 0], ah[i], b0);
                    mma_16816(acc[i][p * 2 + 1], ah[i], b1);
                }
            // pass 2: Al * Bh
            uint32_t al[4][4];
#pragma unroll
            for (int i = 0; i < 4; i++)
                ldmatrix_x4(al[i][0], al[i][1], al[i][2], al[i][3],
                            st + OFF_AL + a_off + i * 16 * ROWB + koff);
#pragma unroll
            for (int i = 0; i < 4; i++)
#pragma unroll
                for (int p = 0; p < 2; p++) {
                    uint32_t b0[2] = {bh[p][0], bh[p][2]};
                    uint32_t b1[2] = {bh[p][1], bh[p][3]};
                    mma_16816(acc[i][p * 2 + 0], al[i], b0);
                    mma_16816(acc[i][p * 2 + 1], al[i], b1);
                }
            // pass 3: Ah * Bl
            uint32_t bl[2][4];
#pragma unroll
            for (int p = 0; p < 2; p++)
                ldmatrix_x4(bl[p][0], bl[p][1], bl[p][2], bl[p][3],
                            st + OFF_BL + b_off + p * 16 * ROWB + koff);
#pragma unroll
            for (int i = 0; i < 4; i++)
#pragma unroll
                for (int p = 0; p < 2; p++) {
                    uint32_t b0[2] = {bl[p][0], bl[p][2]};
                    uint32_t b1[2] = {bl[p][1], bl[p][3]};
                    mma_16816(acc[i][p * 2 + 0], ah[i], b0);
                    mma_16816(acc[i][p * 2 + 1], ah[i], b1);
                }
        }
        __syncthreads();
        if (c + 2 < NCH) load_stage(st, (c + 2) * BK, pAh, pAl, pBh, pBl);
        CP_COMMIT();   // empty group when no loads -> wait count stays exact
    }

    // epilogue: split fp32 accumulators to bf16 hi/lo and store
    __nv_bfloat16* CH = g_qkvH + (size_t)which * NTOK * EMB;
    __nv_bfloat16* CL = g_qkvL + (size_t)which * NTOK * EMB;
    int mbase = row0 + wm * 64 + (lane >> 2);
    int nbase = col0 + wn * 32 + (lane & 3) * 2;
#pragma unroll
    for (int i = 0; i < 4; i++) {
#pragma unroll
        for (int j = 0; j < 4; j++) {
            size_t o0 = (size_t)(mbase + i * 16) * EMB + nbase + j * 8;
            size_t o1 = o0 + (size_t)8 * EMB;
            __nv_bfloat162 h2, l2;
            split_bf16(acc[i][j][0], h2.x, l2.x);
            split_bf16(acc[i][j][1], h2.y, l2.y);
            *(uint32_t*)(CH + o0) = *(uint32_t*)&h2;
            *(uint32_t*)(CL + o0) = *(uint32_t*)&l2;
            split_bf16(acc[i][j][2], h2.x, l2.x);
            split_bf16(acc[i][j][3], h2.y, l2.y);
            *(uint32_t*)(CH + o1) = *(uint32_t*)&h2;
            *(uint32_t*)(CL + o1) = *(uint32_t*)&l2;
        }
    }
}

// ---------------------------------------------------------------------------
// Kernel 4: scores via mma, 3-term split. CTA = (bh, 128q, 128k), one-shot.
// ---------------------------------------------------------------------------
#define QK_ROWB 144
#define QK_TILE (128 * QK_ROWB)          // 18432
#define QK_QH 0
#define QK_QL QK_TILE
#define QK_KH (2 * QK_TILE)
#define QK_KL (3 * QK_TILE)
#define QK_SMEM (4 * QK_TILE)            // 73728

__global__ __launch_bounds__(256, 2) void qk_mma(float* __restrict__ S) {
    extern __shared__ char smem[];
    uint32_t sb = smem_to_u32(smem);
    int t = threadIdx.x;
    int lane = t & 31;
    int w = t >> 5;
    int wm = w >> 1;          // 0..3: 32 q-rows each
    int wn = w & 1;           // 0..1: 64 k-cols each

    int bh = blockIdx.z;
    int b = bh >> 4, h = bh & 15;
    int q0 = blockIdx.y * 128;
    int k0 = blockIdx.x * 128;

    const __nv_bfloat16* QH = g_qkvH + ((size_t)(b * SEQ + q0)) * EMB + h * HDIM;
    const __nv_bfloat16* QL = g_qkvL + ((size_t)(b * SEQ + q0)) * EMB + h * HDIM;
    const __nv_bfloat16* KH = g_qkvH + (size_t)NTOK * EMB + ((size_t)(b * SEQ + k0)) * EMB + h * HDIM;
    const __nv_bfloat16* KL = g_qkvL + (size_t)NTOK * EMB + ((size_t)(b * SEQ + k0)) * EMB + h * HDIM;

    {
        const __nv_bfloat16* srcs[4] = {QH, QL, KH, KL};
        uint32_t dsts[4] = {sb + QK_QH, sb + QK_QL, sb + QK_KH, sb + QK_KL};
#pragma unroll
        for (int j = 0; j < 16; j++) {
            int q = j * 256 + t;          // 0..4095
            int op = q >> 10;
            int r = (q >> 3) & 127;
            int c = q & 7;
            cp_async16(dsts[op] + r * QK_ROWB + c * 16,
                       srcs[op] + (size_t)r * EMB + c * 8);
        }
    }
    CP_COMMIT();
    CP_WAIT0();
    __syncthreads();

    float acc[2][8][4];
#pragma unroll
    for (int i = 0; i < 2; i++)
#pragma unroll
        for (int j = 0; j < 8; j++)
#pragma unroll
            for (int q = 0; q < 4; q++) acc[i][j][q] = 0.0f;

    int lr = lane & 15;
    int lh = lane >> 4;
    uint32_t a_off = (uint32_t)((wm * 32 + lr) * QK_ROWB + lh * 16);
    uint32_t b_off = (uint32_t)((wn * 64 + lr) * QK_ROWB + lh * 16);

#pragma unroll
    for (int ks = 0; ks < 4; ks++) {
        uint32_t koff = ks * 32;
        uint32_t ah[2][4], al[2][4];
#pragma unroll
        for (int mi = 0; mi < 2; mi++) {
            ldmatrix_x4(ah[mi][0], ah[mi][1], ah[mi][2], ah[mi][3],
                        sb + QK_QH + a_off + mi * 16 * QK_ROWB + koff);
            ldmatrix_x4(al[mi][0], al[mi][1], al[mi][2], al[mi][3],
                        sb + QK_QL + a_off + mi * 16 * QK_ROWB + koff);
        }
#pragma unroll
        for (int p = 0; p < 4; p++) {
            uint32_t kh[4], kl[4];
            ldmatrix_x4(kh[0], kh[1], kh[2], kh[3],
                        sb + QK_KH + b_off + p * 16 * QK_ROWB + koff);
            ldmatrix_x4(kl[0], kl[1], kl[2], kl[3],
                        sb + QK_KL + b_off + p * 16 * QK_ROWB + koff);
            uint32_t b0h[2] = {kh[0], kh[2]};
            uint32_t b1h[2] = {kh[1], kh[3]};
            uint32_t b0l[2] = {kl[0], kl[2]};
            uint32_t b1l[2] = {kl[1], kl[3]};
#pragma unroll
            for (int mi = 0; mi < 2; mi++) {
                mma_16816(acc[mi][p * 2 + 0], ah[mi], b0h);
                mma_16816(acc[mi][p * 2 + 1], ah[mi], b1h);
            }
#pragma unroll
            for (int mi = 0; mi < 2; mi++) {
                mma_16816(acc[mi][p * 2 + 0], ah[mi], b0l);
                mma_16816(acc[mi][p * 2 + 1], ah[mi], b1l);
            }
#pragma unroll
            for (int mi = 0; mi < 2; mi++) {
                mma_16816(acc[mi][p * 2 + 0], al[mi], b0h);
                mma_16816(acc[mi][p * 2 + 1], al[mi], b1h);
            }
        }
    }

    float* Sb = S + (size_t)bh * SEQ * SEQ;
    const float scale = 0.125f;
#pragma unroll
    for (int mi = 0; mi < 2; mi++) {
        int r0 = q0 + wm * 32 + mi * 16 + (lane >> 2);
#pragma unroll
        for (int n = 0; n < 8; n++) {
            int col = k0 + wn * 64 + n * 8 + (lane & 3) * 2;
            *(float2*)(Sb + (size_t)r0 * SEQ + col) =
                make_float2(acc[mi][n][0] * scale, acc[mi][n][1] * scale);
            *(float2*)(Sb + (size_t)(r0 + 8) * SEQ + col) =
                make_float2(acc[mi][n][2] * scale, acc[mi][n][3] * scale);
        }
    }
}

// ---------------------------------------------------------------------------
// Kernel 5: in-place row softmax (one CTA per row of length SEQ)
// ---------------------------------------------------------------------------
__global__ __launch_bounds__(256) void softmax_kernel(float* __restrict__ W) {
    float* p = W + (size_t)blockIdx.x * SEQ;
    int t = threadIdx.x;
    float4 a = ((float4*)p)[t];
    float4 b = ((float4*)p)[t + 256];

    float m = fmaxf(fmaxf(fmaxf(a.x, a.y), fmaxf(a.z, a.w)),
                    fmaxf(fmaxf(b.x, b.y), fmaxf(b.z, b.w)));
#pragma unroll
    for (int o = 16; o > 0; o >>= 1) m = fmaxf(m, __shfl_xor_sync(0xffffffffu, m, o));

    __shared__ float red_max[8];
    __shared__ float red_sum[8];
    if ((t & 31) == 0) red_max[t >> 5] = m;
    __syncthreads();
    if (t < 32) {
        float v = (t < 8) ? red_max[t] : -3.402823466e38f;
#pragma unroll
        for (int o = 4; o > 0; o >>= 1) v = fmaxf(v, __shfl_xor_sync(0xffffffffu, v, o));
        if (t == 0) red_max[0] = v;
    }
    __syncthreads();
    m = red_max[0];

    a.x = __expf(a.x - m); a.y = __expf(a.y - m); a.z = __expf(a.z - m); a.w = __expf(a.w - m);
    b.x = __expf(b.x - m); b.y = __expf(b.y - m); b.z = __expf(b.z - m); b.w = __expf(b.w - m);
    float s = a.x + a.y + a.z + a.w + b.x + b.y + b.z + b.w;
#pragma unroll
    for (int o = 16; o > 0; o >>= 1) s += __shfl_xor_sync(0xffffffffu, s, o);
    if ((t & 31) == 0) red_sum[t >> 5] = s;
    __syncthreads();
    if (t < 32) {
        float v = (t < 8) ? red_sum[t] : 0.0f;
#pragma unroll
        for (int o = 4; o > 0; o >>= 1) v += __shfl_xor_sync(0xffffffffu, v, o);
        if (t == 0) red_sum[0] = v;
    }
    __syncthreads();
    float inv = 1.0f / red_sum[0];

    a.x *= inv; a.y *= inv; a.z *= inv; a.w *= inv;
    b.x *= inv; b.y *= inv; b.z *= inv; b.w *= inv;
    ((float4*)p)[t] = a;
    ((float4*)p)[t + 256] = b;
}

// ---------------------------------------------------------------------------
// Kernel 6: O = P @ V via mma, 3-term split (PhVh + PhVl + PlVh).
// V k-major in smem, consumed with ldmatrix.x4.trans.
// ---------------------------------------------------------------------------
#define PV_PROWB 272                     // 128 bf16 + 16B pad
#define PV_VROWB 144
#define PV_PH 0
#define PV_PL (128 * PV_PROWB)                       // 34816
#define PV_VH (2 * 128 * PV_PROWB)                   // 69632
#define PV_VL (2 * 128 * PV_PROWB + 128 * PV_VROWB)  // 88064
#define PV_SMEM (2 * 128 * PV_PROWB + 2 * 128 * PV_VROWB)  // 106496

__global__ __launch_bounds__(256, 2) void pv_mma(const float* __restrict__ P,
                                                 float* __restrict__ O) {
    extern __shared__ char smem[];
    uint32_t sb = smem_to_u32(smem);
    int t = threadIdx.x;
    int lane = t & 31;
    int w = t >> 5;
    int wm = w >> 1;          // 0..3: 32 q-rows
    int wn = w & 1;           // 0..1: 32 d-cols

    int bh = blockIdx.y;
    int b = bh >> 4, h = bh & 15;
    int q0 = blockIdx.x * 128;
    const float* Pb = P + (size_t)bh * SEQ * SEQ + (size_t)q0 * SEQ;
    const __nv_bfloat16* VH = g_qkvH + (size_t)2 * NTOK * EMB + (size_t)(b * SEQ) * EMB + h * HDIM;
    const __nv_bfloat16* VL = g_qkvL + (size_t)2 * NTOK * EMB + (size_t)(b * SEQ) * EMB + h * HDIM;

    float acc[2][4][4];
#pragma unroll
    for (int i = 0; i < 2; i++)
#pragma unroll
        for (int j = 0; j < 4; j++)
#pragma unroll
            for (int q = 0; q < 4; q++) acc[i][j][q] = 0.0f;

    int lr = lane & 15;
    int lh = lane >> 4;
    uint32_t a_off = (uint32_t)((wm * 32 + lr) * PV_PROWB + lh * 16);
    uint32_t vb_off = (uint32_t)(lr * PV_VROWB + (wn * 32 + lh * 8) * 2);

    for (int kc = 0; kc < SEQ / 128; kc++) {
        if (kc) __syncthreads();
#pragma unroll
        for (int j = 0; j < 8; j++) {
            int q = j * 256 + t;       // 0..2047
            int op = q >> 10;
            int r = (q >> 3) & 127;
            int c = q & 7;
            const __nv_bfloat16* src = (op ? VL : VH) + (size_t)(kc * 128 + r) * EMB + c * 8;
            uint32_t dst = sb + (op ? PV_VL : PV_VH) + r * PV_VROWB + c * 16;
            cp_async16(dst, src);
        }
        CP_COMMIT();
#pragma unroll
        for (int j = 0; j < 16; j++) {
            int idx = j * 256 + t;
            int r = idx >> 5;
            int c4 = idx & 31;
            float4 v = *(const float4*)(Pb + (size_t)r * SEQ + kc * 128 + c4 * 4);
            __nv_bfloat162 h01, l01, h23, l23;
            split_bf16(v.x, h01.x, l01.x);
            split_bf16(v.y, h01.y, l01.y);
            split_bf16(v.z, h23.x, l23.x);
            split_bf16(v.w, h23.y, l23.y);
            uint32_t off = (uint32_t)(r * PV_PROWB + c4 * 8);
            *(uint2*)(smem + PV_PH + off) = make_uint2(*(uint32_t*)&h01, *(uint32_t*)&h23);
            *(uint2*)(smem + PV_PL + off) = make_uint2(*(uint32_t*)&l01, *(uint32_t*)&l23);
        }
        CP_WAIT0();
        __syncthreads();

#pragma unroll
        for (int ks = 0; ks < 8; ks++) {
            uint32_t koff = ks * 32;
            uint32_t ph[2][4], pl[2][4];
#pragma unroll
            for (int mi = 0; mi < 2; mi++) {
                ldmatrix_x4(ph[mi][0], ph[mi][1], ph[mi][2], ph[mi][3],
                            sb + PV_PH + a_off + mi * 16 * PV_PROWB + koff);
                ldmatrix_x4(pl[mi][0], pl[mi][1], pl[mi][2], pl[mi][3],
                            sb + PV_PL + a_off + mi * 16 * PV_PROWB + koff);
            }
            uint32_t vrow = (uint32_t)(ks * 16 * PV_VROWB);
            uint32_t vh[2][4], vl[2][4];
#pragma unroll
            for (int g = 0; g < 2; g++) {
                ldmatrix_x4_trans(vh[g][0], vh[g][1], vh[g][2], vh[g][3],
                                  sb + PV_VH + vb_off + vrow + g * 32);
                ldmatrix_x4_trans(vl[g][0], vl[g][1], vl[g][2], vl[g][3],
                                  sb + PV_VL + vb_off + vrow + g * 32);
            }
#pragma unroll
            for (int mi = 0; mi < 2; mi++)
#pragma unroll
                for (int g = 0; g < 2; g++) {
                    uint32_t b0[2] = {vh[g][0], vh[g][1]};
                    uint32_t b1[2] = {vh[g][2], vh[g][3]};
                    mma_16816(acc[mi][g * 2 + 0], ph[mi], b0);
                    mma_16816(acc[mi][g * 2 + 1], ph[mi], b1);
                }
#pragma unroll
            for (int mi = 0; mi < 2; mi++)
#pragma unroll
                for (int g = 0; g < 2; g++) {
                    uint32_t b0[2] = {vl[g][0], vl[g][1]};
                    uint32_t b1[2] = {vl[g][2], vl[g][3]};
                    mma_16816(acc[mi][g * 2 + 0], ph[mi], b0);
                    mma_16816(acc[mi][g * 2 + 1], ph[mi], b1);
                }
#pragma unroll
            for (int mi = 0; mi < 2; mi++)
#pragma unroll
                for (int g = 0; g < 2; g++) {
                    uint32_t b0[2] = {vh[g][0], vh[g][1]};
                    uint32_t b1[2] = {vh[g][2], vh[g][3]};
                    mma_16816(acc[mi][g * 2 + 0], pl[mi], b0);
                    mma_16816(acc[mi][g * 2 + 1], pl[mi], b1);
                }
        }
    }

    float* Ob = O + (size_t)(b * SEQ) * EMB + h * HDIM;
#pragma unroll
    for (int mi = 0; mi < 2; mi++) {
        int r0 = q0 + wm * 32 + mi * 16 + (lane >> 2);
#pragma unroll
        for (int n = 0; n < 4; n++) {
            int col = wn * 32 + n * 8 + (lane & 3) * 2;
            *(float2*)(Ob + (size_t)r0 * EMB + col) =
                make_float2(acc[mi][n][0], acc[mi][n][1]);
            *(float2*)(Ob + (size_t)(r0 + 8) * EMB + col) =
                make_float2(acc[mi][n][2], acc[mi][n][3]);
        }
    }
}

// ---------------------------------------------------------------------------
extern "C" void kernel_launch(void* const* d_in, const int* in_sizes, int n_in,
                              void* d_out, int out_size) {
    (void)in_sizes; (void)n_in; (void)out_size;
    float* out = (float*)d_out;                          // attn_output [B, L, E]
    float* attnw = out + (size_t)NTOK * EMB;             // attn_weights [B, H, L, L]

    Ptr3 X;
    X.p[0] = (const float*)d_in[0];
    X.p[1] = (const float*)d_in[1];
    X.p[2] = (const float*)d_in[2];
    PtrW Wp;
    for (int p = 0; p < 3; p++) {
        Wp.base[p]   = (const float*)d_in[3 + 3 * p];
        Wp.spline[p] = (const float*)d_in[4 + 3 * p];
        Wp.scaler[p] = (const float*)d_in[5 + 3 * p];
    }

    cudaFuncSetAttribute(gemm_kan_mma, cudaFuncAttributeMaxDynamicSharedMemorySize, GEMM_SMEM);
    cudaFuncSetAttribute(qk_mma, cudaFuncAttributeMaxDynamicSharedMemorySize, QK_SMEM);
    cudaFuncSetAttribute(pv_mma, cudaFuncAttributeMaxDynamicSharedMemorySize, PV_SMEM);

    phi_split_all<<<dim3((NTOK * EMB) / 256, 3), 256>>>(X);
    wprep_split_all<<<dim3((EMB * EMB) / 256, 3), 256>>>(Wp);
    gemm_kan_mma<<<dim3(EMB / BN, NTOK / BM, 3), 256, GEMM_SMEM>>>();
    qk_mma<<<dim3(SEQ / 128, SEQ / 128, BATCH * HEADS), 256, QK_SMEM>>>(attnw);
    softmax_kernel<<<BATCH * HEADS * SEQ, 256>>>(attnw);
    pv_mma<<<dim3(SEQ / 128, BATCH * HEADS), 256, PV_SMEM>>>(attnw, out);
}

// round 12
// speedup vs baseline: 1.1027x; 1.1027x over previous
#include <cuda_runtime.h>
#include <cuda_bf16.h>
#include <cstdint>
#include <cstddef>

// Problem constants
#define BATCH 2
#define SEQ   2048
#define EMB   1024
#define HEADS 16
#define HDIM  64
#define NTOK  (BATCH * SEQ)          // 4096
#define KDIM  (EMB * 8)              // 8192 expanded features
#define NB    7                      // spline bases per feature

// ---------------- scratch (static device globals; no allocation) ------------
__device__ uint4 g_phiH4[(size_t)3 * NTOK * KDIM / 8];   // bf16 hi, per projection
__device__ uint4 g_phiL4[(size_t)3 * NTOK * KDIM / 8];   // bf16 lo
__device__ uint4 g_WH4[(size_t)3 * EMB * KDIM / 8];
__device__ uint4 g_WL4[(size_t)3 * EMB * KDIM / 8];
__device__ __nv_bfloat16 g_qkvH[(size_t)3 * NTOK * EMB];
__device__ __nv_bfloat16 g_qkvL[(size_t)3 * NTOK * EMB];

struct Ptr3 { const float* p[3]; };
struct PtrW { const float* base[3]; const float* spline[3]; const float* scaler[3]; };

// =====================  PTX helpers (compute_103-safe) ======================
__device__ __forceinline__ uint32_t smem_to_u32(const void* p) {
    uint32_t a;
    asm("{ .reg .u64 t; cvta.to.shared.u64 t, %1; cvt.u32.u64 %0, t; }" : "=r"(a) : "l"(p));
    return a;
}
__device__ __forceinline__ void cp_async16(uint32_t dst, const void* src) {
    asm volatile("cp.async.cg.shared.global [%0], [%1], 16;" :: "r"(dst), "l"(src));
}
#define CP_COMMIT() asm volatile("cp.async.commit_group;" ::: "memory")
#define CP_WAIT1()  asm volatile("cp.async.wait_group 1;" ::: "memory")
#define CP_WAIT0()  asm volatile("cp.async.wait_group 0;" ::: "memory")

__device__ __forceinline__ void ldmatrix_x4(uint32_t& r0, uint32_t& r1,
                                            uint32_t& r2, uint32_t& r3, uint32_t addr) {
    asm volatile("ldmatrix.sync.aligned.m8n8.x4.shared.b16 {%0,%1,%2,%3}, [%4];"
                 : "=r"(r0), "=r"(r1), "=r"(r2), "=r"(r3) : "r"(addr));
}
__device__ __forceinline__ void ldmatrix_x4_trans(uint32_t& r0, uint32_t& r1,
                                                  uint32_t& r2, uint32_t& r3, uint32_t addr) {
    asm volatile("ldmatrix.sync.aligned.m8n8.x4.trans.shared.b16 {%0,%1,%2,%3}, [%4];"
                 : "=r"(r0), "=r"(r1), "=r"(r2), "=r"(r3) : "r"(addr));
}
__device__ __forceinline__ void mma_16816(float* d, const uint32_t* a, const uint32_t* b) {
    asm volatile(
        "mma.sync.aligned.m16n8k16.row.col.f32.bf16.bf16.f32 "
        "{%0,%1,%2,%3}, {%4,%5,%6,%7}, {%8,%9}, {%0,%1,%2,%3};"
        : "+f"(d[0]), "+f"(d[1]), "+f"(d[2]), "+f"(d[3])
        : "r"(a[0]), "r"(a[1]), "r"(a[2]), "r"(a[3]), "r"(b[0]), "r"(b[1]));
}
__device__ __forceinline__ void split_bf16(float v, __nv_bfloat16& h, __nv_bfloat16& l) {
    h = __float2bfloat16(v);
    l = __float2bfloat16(v - __bfloat162float(h));
}

// ---------------------------------------------------------------------------
// Kernel 1: expand X -> phi (x, B0..B6) bf16 hi/lo, [proj][NTOK, KDIM]
// ---------------------------------------------------------------------------
__global__ __launch_bounds__(256) void phi_split_all(Ptr3 X) {
    int proj = blockIdx.y;
    int idx = blockIdx.x * blockDim.x + threadIdx.x;
    float x = X.p[proj][idx];

    float b[10];
#pragma unroll
    for (int t = 0; t < 10; t++) {
        float gt = -2.5f + 0.5f * (float)t;
        b[t] = (x >= gt && x < gt + 0.5f) ? 1.0f : 0.0f;
    }
#pragma unroll
    for (int p = 1; p <= 3; p++) {
#pragma unroll
        for (int t = 0; t < 10; t++) {
            if (t + p < 10) {
                float gt   = -2.5f + 0.5f * (float)t;
                float gtp  = gt + 0.5f * (float)p;
                float gtp1 = gtp + 0.5f;
                float gt1  = gt + 0.5f;
                float left  = (x - gt)   / (gtp - gt);
                float right = (gtp1 - x) / (gtp1 - gt1);
                b[t] = left * b[t] + right * b[t + 1];
            }
        }
    }
    float v[8] = {x, b[0], b[1], b[2], b[3], b[4], b[5], b[6]};
    __nv_bfloat16 hi[8], lo[8];
#pragma unroll
    for (int j = 0; j < 8; j++) split_bf16(v[j], hi[j], lo[j]);
    size_t o = (size_t)proj * (NTOK * (KDIM / 8)) + idx;
    g_phiH4[o] = *(uint4*)hi;
    g_phiL4[o] = *(uint4*)lo;
}

// ---------------------------------------------------------------------------
// Kernel 2: combined weight W[proj][EMB, KDIM] row-major, bf16 hi/lo
// ---------------------------------------------------------------------------
__global__ __launch_bounds__(256) void wprep_split_all(PtrW Wp) {
    int proj = blockIdx.y;
    int idx = blockIdx.x * blockDim.x + threadIdx.x;
    int i = idx & (EMB - 1);
    int m = idx >> 10;
    size_t mi = (size_t)m * EMB + i;
    float v[8];
    v[0] = Wp.base[proj][mi];
    float sc = Wp.scaler[proj][mi];
    const float* sp = Wp.spline[proj] + mi * NB;
#pragma unroll
    for (int j = 0; j < NB; j++) v[1 + j] = sp[j] * sc;

    __nv_bfloat16 hi[8], lo[8];
#pragma unroll
    for (int j = 0; j < 8; j++) split_bf16(v[j], hi[j], lo[j]);
    size_t o = (size_t)proj * (EMB * (KDIM / 8)) + (size_t)m * (KDIM / 8) + i;
    g_WH4[o] = *(uint4*)hi;
    g_WL4[o] = *(uint4*)lo;
}

// ---------------------------------------------------------------------------
// Kernel 3: mma.sync GEMM  C = phi @ W^T, 3-term bf16 split.
// CTA tile 128x256x64, 8 warps (2x4), warp tile 64x64.
// 2-stage cp.async, 108KB/stage (rows 128B padded to 144B, conflict-free).
// One launch, all 3 projections: grid (4, 32, 3).
// ---------------------------------------------------------------------------
#define BM 128
#define BN 256
#define BK 64
#define NCH (KDIM / BK)                 // 128
#define ROWB 144                        // 64 bf16 = 128B + 16B pad
#define A_TILE (BM * ROWB)              // 18432
#define B_TILE (BN * ROWB)              // 36864
#define OFF_AH 0
#define OFF_AL A_TILE
#define OFF_BH (2 * A_TILE)
#define OFF_BL (2 * A_TILE + B_TILE)
#define STAGE (2 * A_TILE + 2 * B_TILE) // 110592
#define GEMM_SMEM (2 * STAGE)           // 221184

__device__ __forceinline__ void load_stage(uint32_t sbase, int k0,
                                           const __nv_bfloat16* pAh, const __nv_bfloat16* pAl,
                                           const __nv_bfloat16* pBh, const __nv_bfloat16* pBl) {
    int t = threadIdx.x;
#pragma unroll
    for (int j = 0; j < 24; j++) {
        int idx = j * 256 + t;          // 0..6143
        const __nv_bfloat16* src;
        uint32_t dst;
        if (idx < 1024) {               // Ah: 128 rows x 8 chunks
            int r = idx >> 3, c = idx & 7;
            src = pAh + (size_t)r * KDIM + k0 + c * 8;
            dst = sbase + OFF_AH + r * ROWB + c * 16;
        } else if (idx < 2048) {        // Al
            int lq = idx - 1024;
            int r = lq >> 3, c = lq & 7;
            src = pAl + (size_t)r * KDIM + k0 + c * 8;
            dst = sbase + OFF_AL + r * ROWB + c * 16;
        } else if (idx < 4096) {        // Bh: 256 rows x 8 chunks
            int lq = idx - 2048;
            int r = lq >> 3, c = lq & 7;
            src = pBh + (size_t)r * KDIM + k0 + c * 8;
            dst = sbase + OFF_BH + r * ROWB + c * 16;
        } else {                        // Bl
            int lq = idx - 4096;
            int r = lq >> 3, c = lq & 7;
            src = pBl + (size_t)r * KDIM + k0 + c * 8;
            dst = sbase + OFF_BL + r * ROWB + c * 16;
        }
        cp_async16(dst, src);
    }
}

__global__ __launch_bounds__(256, 1) void gemm_kan_mma() {
    extern __shared__ char smem[];
    uint32_t sb = smem_to_u32(smem);
    int t = threadIdx.x;
    int lane = t & 31;
    int w = t >> 5;
    int wm = w >> 2;          // 0..1 : 64 m-rows
    int wn = w & 3;           // 0..3 : 64 n-cols

    int which = blockIdx.z;
    int row0 = blockIdx.y * BM;
    int col0 = blockIdx.x * BN;
    const __nv_bfloat16* pAh = (const __nv_bfloat16*)g_phiH4 +
        (size_t)which * NTOK * KDIM + (size_t)row0 * KDIM;
    const __nv_bfloat16* pAl = (const __nv_bfloat16*)g_phiL4 +
        (size_t)which * NTOK * KDIM + (size_t)row0 * KDIM;
    const __nv_bfloat16* pBh = (const __nv_bfloat16*)g_WH4 +
        (size_t)which * EMB * KDIM + (size_t)col0 * KDIM;
    const __nv_bfloat16* pBl = (const __nv_bfloat16*)g_WL4 +
        (size_t)which * EMB * KDIM + (size_t)col0 * KDIM;

    load_stage(sb + 0 * STAGE, 0 * BK, pAh, pAl, pBh, pBl); CP_COMMIT();
    load_stage(sb + 1 * STAGE, 1 * BK, pAh, pAl, pBh, pBl); CP_COMMIT();

    float acc[4][8][4];
#pragma unroll
    for (int i = 0; i < 4; i++)
#pragma unroll
        for (int j = 0; j < 8; j++)
#pragma unroll
            for (int q = 0; q < 4; q++) acc[i][j][q] = 0.0f;

    int lr = lane & 15;
    int lh = lane >> 4;
    uint32_t a_off = (uint32_t)((wm * 64 + lr) * ROWB + lh * 16);
    uint32_t b_off = (uint32_t)((wn * 64 + lr) * ROWB + lh * 16);

    for (int c = 0; c < NCH; c++) {
        uint32_t st = sb + (c & 1) * STAGE;
        CP_WAIT1();
        __syncthreads();

#pragma unroll
        for (int ks = 0; ks < 4; ks++) {
            uint32_t koff = ks * 32;
            uint32_t ah[4][4], al[4][4];
#pragma unroll
            for (int i = 0; i < 4; i++) {
                ldmatrix_x4(ah[i][0], ah[i][1], ah[i][2], ah[i][3],
                            st + OFF_AH + a_off + i * 16 * ROWB + koff);
                ldmatrix_x4(al[i][0], al[i][1], al[i][2], al[i][3],
                            st + OFF_AL + a_off + i * 16 * ROWB + koff);
            }
            uint32_t bh[4][4], bl[4][4];
#pragma unroll
            for (int p = 0; p < 4; p++) {
                ldmatrix_x4(bh[p][0], bh[p][1], bh[p][2], bh[p][3],
                            st + OFF_BH + b_off + p * 16 * ROWB + koff);
                ldmatrix_x4(bl[p][0], bl[p][1], bl[p][2], bl[p][3],
                            st + OFF_BL + b_off + p * 16 * ROWB + koff);
            }
            // pass 1: Ah * Bh
#pragma unroll
            for (int i = 0; i < 4; i++)
#pragma unroll
                for (int p = 0; p < 4; p++) {
                    uint32_t b0[2] = {bh[p][0], bh[p][2]};
                    uint32_t b1[2] = {bh[p][1], bh[p][3]};
                    mma_16816(acc[i][p * 2 + 0], ah[i], b0);
                    mma_16816(acc[i][p * 2 + 1], ah[i], b1);
                }
            // pass 2: Ah * Bl
#pragma unroll
            for (int i = 0; i < 4; i++)
#pragma unroll
                for (int p = 0; p < 4; p++) {
                    uint32_t b0[2] = {bl[p][0], bl[p][2]};
                    uint32_t b1[2] = {bl[p][1], bl[p][3]};
                    mma_16816(acc[i][p * 2 + 0], ah[i], b0);
                    mma_16816(acc[i][p * 2 + 1], ah[i], b1);
                }
            // pass 3: Al * Bh
#pragma unroll
            for (int i = 0; i < 4; i++)
#pragma unroll
                for (int p = 0; p < 4; p++) {
                    uint32_t b0[2] = {bh[p][0], bh[p][2]};
                    uint32_t b1[2] = {bh[p][1], bh[p][3]};
                    mma_16816(acc[i][p * 2 + 0], al[i], b0);
                    mma_16816(acc[i][p * 2 + 1], al[i], b1);
                }
        }
        __syncthreads();
        if (c + 2 < NCH) load_stage(st, (c + 2) * BK, pAh, pAl, pBh, pBl);
        CP_COMMIT();   // empty group when no loads -> wait count stays exact
    }

    // epilogue: split fp32 accumulators to bf16 hi/lo and store
    __nv_bfloat16* CH = g_qkvH + (size_t)which * NTOK * EMB;
    __nv_bfloat16* CL = g_qkvL + (size_t)which * NTOK * EMB;
    int mbase = row0 + wm * 64 + (lane >> 2);
    int nbase = col0 + wn * 64 + (lane & 3) * 2;
#pragma unroll
    for (int i = 0; i < 4; i++) {
#pragma unroll
        for (int j = 0; j < 8; j++) {
            size_t o0 = (size_t)(mbase + i * 16) * EMB + nbase + j * 8;
            size_t o1 = o0 + (size_t)8 * EMB;
            __nv_bfloat162 h2, l2;
            split_bf16(acc[i][j][0], h2.x, l2.x);
            split_bf16(acc[i][j][1], h2.y, l2.y);
            *(uint32_t*)(CH + o0) = *(uint32_t*)&h2;
            *(uint32_t*)(CL + o0) = *(uint32_t*)&l2;
            split_bf16(acc[i][j][2], h2.x, l2.x);
            split_bf16(acc[i][j][3], h2.y, l2.y);
            *(uint32_t*)(CH + o1) = *(uint32_t*)&h2;
            *(uint32_t*)(CL + o1) = *(uint32_t*)&l2;
        }
    }
}

// ---------------------------------------------------------------------------
// Kernel 4: scores via mma, 3-term split. CTA = (bh, 128q, 128k), one-shot.
// ---------------------------------------------------------------------------
#define QK_ROWB 144
#define QK_TILE (128 * QK_ROWB)
#define QK_QH 0
#define QK_QL QK_TILE
#define QK_KH (2 * QK_TILE)
#define QK_KL (3 * QK_TILE)
#define QK_SMEM (4 * QK_TILE)            // 73728

__global__ __launch_bounds__(256, 2) void qk_mma(float* __restrict__ S) {
    extern __shared__ char smem[];
    uint32_t sb = smem_to_u32(smem);
    int t = threadIdx.x;
    int lane = t & 31;
    int w = t >> 5;
    int wm = w >> 1;
    int wn = w & 1;

    int bh = blockIdx.z;
    int b = bh >> 4, h = bh & 15;
    int q0 = blockIdx.y * 128;
    int k0 = blockIdx.x * 128;

    const __nv_bfloat16* QH = g_qkvH + ((size_t)(b * SEQ + q0)) * EMB + h * HDIM;
    const __nv_bfloat16* QL = g_qkvL + ((size_t)(b * SEQ + q0)) * EMB + h * HDIM;
    const __nv_bfloat16* KH = g_qkvH + (size_t)NTOK * EMB + ((size_t)(b * SEQ + k0)) * EMB + h * HDIM;
    const __nv_bfloat16* KL = g_qkvL + (size_t)NTOK * EMB + ((size_t)(b * SEQ + k0)) * EMB + h * HDIM;

    {
        const __nv_bfloat16* srcs[4] = {QH, QL, KH, KL};
        uint32_t dsts[4] = {sb + QK_QH, sb + QK_QL, sb + QK_KH, sb + QK_KL};
#pragma unroll
        for (int j = 0; j < 16; j++) {
            int q = j * 256 + t;
            int op = q >> 10;
            int r = (q >> 3) & 127;
            int c = q & 7;
            cp_async16(dsts[op] + r * QK_ROWB + c * 16,
                       srcs[op] + (size_t)r * EMB + c * 8);
        }
    }
    CP_COMMIT();
    CP_WAIT0();
    __syncthreads();

    float acc[2][8][4];
#pragma unroll
    for (int i = 0; i < 2; i++)
#pragma unroll
        for (int j = 0; j < 8; j++)
#pragma unroll
            for (int q = 0; q < 4; q++) acc[i][j][q] = 0.0f;

    int lr = lane & 15;
    int lh = lane >> 4;
    uint32_t a_off = (uint32_t)((wm * 32 + lr) * QK_ROWB + lh * 16);
    uint32_t b_off = (uint32_t)((wn * 64 + lr) * QK_ROWB + lh * 16);

#pragma unroll
    for (int ks = 0; ks < 4; ks++) {
        uint32_t koff = ks * 32;
        uint32_t ah[2][4], al[2][4];
#pragma unroll
        for (int mi = 0; mi < 2; mi++) {
            ldmatrix_x4(ah[mi][0], ah[mi][1], ah[mi][2], ah[mi][3],
                        sb + QK_QH + a_off + mi * 16 * QK_ROWB + koff);
            ldmatrix_x4(al[mi][0], al[mi][1], al[mi][2], al[mi][3],
                        sb + QK_QL + a_off + mi * 16 * QK_ROWB + koff);
        }
#pragma unroll
        for (int p = 0; p < 4; p++) {
            uint32_t kh[4], kl[4];
            ldmatrix_x4(kh[0], kh[1], kh[2], kh[3],
                        sb + QK_KH + b_off + p * 16 * QK_ROWB + koff);
            ldmatrix_x4(kl[0], kl[1], kl[2], kl[3],
                        sb + QK_KL + b_off + p * 16 * QK_ROWB + koff);
            uint32_t b0h[2] = {kh[0], kh[2]};
            uint32_t b1h[2] = {kh[1], kh[3]};
            uint32_t b0l[2] = {kl[0], kl[2]};
            uint32_t b1l[2] = {kl[1], kl[3]};
#pragma unroll
            for (int mi = 0; mi < 2; mi++) {
                mma_16816(acc[mi][p * 2 + 0], ah[mi], b0h);
                mma_16816(acc[mi][p * 2 + 1], ah[mi], b1h);
            }
#pragma unroll
            for (int mi = 0; mi < 2; mi++) {
                mma_16816(acc[mi][p * 2 + 0], ah[mi], b0l);
                mma_16816(acc[mi][p * 2 + 1], ah[mi], b1l);
            }
#pragma unroll
            for (int mi = 0; mi < 2; mi++) {
                mma_16816(acc[mi][p * 2 + 0], al[mi], b0h);
                mma_16816(acc[mi][p * 2 + 1], al[mi], b1h);
            }
        }
    }

    float* Sb = S + (size_t)bh * SEQ * SEQ;
    const float scale = 0.125f;
#pragma unroll
    for (int mi = 0; mi < 2; mi++) {
        int r0 = q0 + wm * 32 + mi * 16 + (lane >> 2);
#pragma unroll
        for (int n = 0; n < 8; n++) {
            int col = k0 + wn * 64 + n * 8 + (lane & 3) * 2;
            *(float2*)(Sb + (size_t)r0 * SEQ + col) =
                make_float2(acc[mi][n][0] * scale, acc[mi][n][1] * scale);
            *(float2*)(Sb + (size_t)(r0 + 8) * SEQ + col) =
                make_float2(acc[mi][n][2] * scale, acc[mi][n][3] * scale);
        }
    }
}

// ---------------------------------------------------------------------------
// Kernel 5: in-place row softmax (one CTA per row of length SEQ)
// ---------------------------------------------------------------------------
__global__ __launch_bounds__(256) void softmax_kernel(float* __restrict__ W) {
    float* p = W + (size_t)blockIdx.x * SEQ;
    int t = threadIdx.x;
    float4 a = ((float4*)p)[t];
    float4 b = ((float4*)p)[t + 256];

    float m = fmaxf(fmaxf(fmaxf(a.x, a.y), fmaxf(a.z, a.w)),
                    fmaxf(fmaxf(b.x, b.y), fmaxf(b.z, b.w)));
#pragma unroll
    for (int o = 16; o > 0; o >>= 1) m = fmaxf(m, __shfl_xor_sync(0xffffffffu, m, o));

    __shared__ float red_max[8];
    __shared__ float red_sum[8];
    if ((t & 31) == 0) red_max[t >> 5] = m;
    __syncthreads();
    if (t < 32) {
        float v = (t < 8) ? red_max[t] : -3.402823466e38f;
#pragma unroll
        for (int o = 4; o > 0; o >>= 1) v = fmaxf(v, __shfl_xor_sync(0xffffffffu, v, o));
        if (t == 0) red_max[0] = v;
    }
    __syncthreads();
    m = red_max[0];

    a.x = __expf(a.x - m); a.y = __expf(a.y - m); a.z = __expf(a.z - m); a.w = __expf(a.w - m);
    b.x = __expf(b.x - m); b.y = __expf(b.y - m); b.z = __expf(b.z - m); b.w = __expf(b.w - m);
    float s = a.x + a.y + a.z + a.w + b.x + b.y + b.z + b.w;
#pragma unroll
    for (int o = 16; o > 0; o >>= 1) s += __shfl_xor_sync(0xffffffffu, s, o);
    if ((t & 31) == 0) red_sum[t >> 5] = s;
    __syncthreads();
    if (t < 32) {
        float v = (t < 8) ? red_sum[t] : 0.0f;
#pragma unroll
        for (int o = 4; o > 0; o >>= 1) v += __shfl_xor_sync(0xffffffffu, v, o);
        if (t == 0) red_sum[0] = v;
    }
    __syncthreads();
    float inv = 1.0f / red_sum[0];

    a.x *= inv; a.y *= inv; a.z *= inv; a.w *= inv;
    b.x *= inv; b.y *= inv; b.z *= inv; b.w *= inv;
    ((float4*)p)[t] = a;
    ((float4*)p)[t + 256] = b;
}

// ---------------------------------------------------------------------------
// Kernel 6: O = P @ V via mma, 3-term split (PhVh + PhVl + PlVh).
// ---------------------------------------------------------------------------
#define PV_PROWB 272
#define PV_VROWB 144
#define PV_PH 0
#define PV_PL (128 * PV_PROWB)
#define PV_VH (2 * 128 * PV_PROWB)
#define PV_VL (2 * 128 * PV_PROWB + 128 * PV_VROWB)
#define PV_SMEM (2 * 128 * PV_PROWB + 2 * 128 * PV_VROWB)  // 106496

__global__ __launch_bounds__(256, 2) void pv_mma(const float* __restrict__ P,
                                                 float* __restrict__ O) {
    extern __shared__ char smem[];
    uint32_t sb = smem_to_u32(smem);
    int t = threadIdx.x;
    int lane = t & 31;
    int w = t >> 5;
    int wm = w >> 1;
    int wn = w & 1;

    int bh = blockIdx.y;
    int b = bh >> 4, h = bh & 15;
    int q0 = blockIdx.x * 128;
    const float* Pb = P + (size_t)bh * SEQ * SEQ + (size_t)q0 * SEQ;
    const __nv_bfloat16* VH = g_qkvH + (size_t)2 * NTOK * EMB + (size_t)(b * SEQ) * EMB + h * HDIM;
    const __nv_bfloat16* VL = g_qkvL + (size_t)2 * NTOK * EMB + (size_t)(b * SEQ) * EMB + h * HDIM;

    float acc[2][4][4];
#pragma unroll
    for (int i = 0; i < 2; i++)
#pragma unroll
        for (int j = 0; j < 4; j++)
#pragma unroll
            for (int q = 0; q < 4; q++) acc[i][j][q] = 0.0f;

    int lr = lane & 15;
    int lh = lane >> 4;
    uint32_t a_off = (uint32_t)((wm * 32 + lr) * PV_PROWB + lh * 16);
    uint32_t vb_off = (uint32_t)(lr * PV_VROWB + (wn * 32 + lh * 8) * 2);

    for (int kc = 0; kc < SEQ / 128; kc++) {
        if (kc) __syncthreads();
#pragma unroll
        for (int j = 0; j < 8; j++) {
            int q = j * 256 + t;
            int op = q >> 10;
            int r = (q >> 3) & 127;
            int c = q & 7;
            const __nv_bfloat16* src = (op ? VL : VH) + (size_t)(kc * 128 + r) * EMB + c * 8;
            uint32_t dst = sb + (op ? PV_VL : PV_VH) + r * PV_VROWB + c * 16;
            cp_async16(dst, src);
        }
        CP_COMMIT();
#pragma unroll
        for (int j = 0; j < 16; j++) {
            int idx = j * 256 + t;
            int r = idx >> 5;
            int c4 = idx & 31;
            float4 v = *(const float4*)(Pb + (size_t)r * SEQ + kc * 128 + c4 * 4);
            __nv_bfloat162 h01, l01, h23, l23;
            split_bf16(v.x, h01.x, l01.x);
            split_bf16(v.y, h01.y, l01.y);
            split_bf16(v.z, h23.x, l23.x);
            split_bf16(v.w, h23.y, l23.y);
            uint32_t off = (uint32_t)(r * PV_PROWB + c4 * 8);
            *(uint2*)(smem + PV_PH + off) = make_uint2(*(uint32_t*)&h01, *(uint32_t*)&h23);
            *(uint2*)(smem + PV_PL + off) = make_uint2(*(uint32_t*)&l01, *(uint32_t*)&l23);
        }
        CP_WAIT0();
        __syncthreads();

#pragma unroll
        for (int ks = 0; ks < 8; ks++) {
            uint32_t koff = ks * 32;
            uint32_t ph[2][4], pl[2][4];
#pragma unroll
            for (int mi = 0; mi < 2; mi++) {
                ldmatrix_x4(ph[mi][0], ph[mi][1], ph[mi][2], ph[mi][3],
                            sb + PV_PH + a_off + mi * 16 * PV_PROWB + koff);
                ldmatrix_x4(pl[mi][0], pl[mi][1], pl[mi][2], pl[mi][3],
                            sb + PV_PL + a_off + mi * 16 * PV_PROWB + koff);
            }
            uint32_t vrow = (uint32_t)(ks * 16 * PV_VROWB);
            uint32_t vh[2][4], vl[2][4];
#pragma unroll
            for (int g = 0; g < 2; g++) {
                ldmatrix_x4_trans(vh[g][0], vh[g][1], vh[g][2], vh[g][3],
                                  sb + PV_VH + vb_off + vrow + g * 32);
                ldmatrix_x4_trans(vl[g][0], vl[g][1], vl[g][2], vl[g][3],
                                  sb + PV_VL + vb_off + vrow + g * 32);
            }
#pragma unroll
            for (int mi = 0; mi < 2; mi++)
#pragma unroll
                for (int g = 0; g < 2; g++) {
                    uint32_t b0[2] = {vh[g][0], vh[g][1]};
                    uint32_t b1[2] = {vh[g][2], vh[g][3]};
                    mma_16816(acc[mi][g * 2 + 0], ph[mi], b0);
                    mma_16816(acc[mi][g * 2 + 1], ph[mi], b1);
                }
#pragma unroll
            for (int mi = 0; mi < 2; mi++)
#pragma unroll
                for (int g = 0; g < 2; g++) {
                    uint32_t b0[2] = {vl[g][0], vl[g][1]};
                    uint32_t b1[2] = {vl[g][2], vl[g][3]};
                    mma_16816(acc[mi][g * 2 + 0], ph[mi], b0);
                    mma_16816(acc[mi][g * 2 + 1], ph[mi], b1);
                }
#pragma unroll
            for (int mi = 0; mi < 2; mi++)
#pragma unroll
                for (int g = 0; g < 2; g++) {
                    uint32_t b0[2] = {vh[g][0], vh[g][1]};
                    uint32_t b1[2] = {vh[g][2], vh[g][3]};
                    mma_16816(acc[mi][g * 2 + 0], pl[mi], b0);
                    mma_16816(acc[mi][g * 2 + 1], pl[mi], b1);
                }
        }
    }

    float* Ob = O + (size_t)(b * SEQ) * EMB + h * HDIM;
#pragma unroll
    for (int mi = 0; mi < 2; mi++) {
        int r0 = q0 + wm * 32 + mi * 16 + (lane >> 2);
#pragma unroll
        for (int n = 0; n < 4; n++) {
            int col = wn * 32 + n * 8 + (lane & 3) * 2;
            *(float2*)(Ob + (size_t)r0 * EMB + col) =
                make_float2(acc[mi][n][0], acc[mi][n][1]);
            *(float2*)(Ob + (size_t)(r0 + 8) * EMB + col) =
                make_float2(acc[mi][n][2], acc[mi][n][3]);
        }
    }
}

// ---------------------------------------------------------------------------
extern "C" void kernel_launch(void* const* d_in, const int* in_sizes, int n_in,
                              void* d_out, int out_size) {
    (void)in_sizes; (void)n_in; (void)out_size;
    float* out = (float*)d_out;                          // attn_output [B, L, E]
    float* attnw = out + (size_t)NTOK * EMB;             // attn_weights [B, H, L, L]

    Ptr3 X;
    X.p[0] = (const float*)d_in[0];
    X.p[1] = (const float*)d_in[1];
    X.p[2] = (const float*)d_in[2];
    PtrW Wp;
    for (int p = 0; p < 3; p++) {
        Wp.base[p]   = (const float*)d_in[3 + 3 * p];
        Wp.spline[p] = (const float*)d_in[4 + 3 * p];
        Wp.scaler[p] = (const float*)d_in[5 + 3 * p];
    }

    cudaFuncSetAttribute(gemm_kan_mma, cudaFuncAttributeMaxDynamicSharedMemorySize, GEMM_SMEM);
    cudaFuncSetAttribute(qk_mma, cudaFuncAttributeMaxDynamicSharedMemorySize, QK_SMEM);
    cudaFuncSetAttribute(pv_mma, cudaFuncAttributeMaxDynamicSharedMemorySize, PV_SMEM);

    phi_split_all<<<dim3((NTOK * EMB) / 256, 3), 256>>>(X);
    wprep_split_all<<<dim3((EMB * EMB) / 256, 3), 256>>>(Wp);
    gemm_kan_mma<<<dim3(EMB / BN, NTOK / BM, 3), 256, GEMM_SMEM>>>();
    qk_mma<<<dim3(SEQ / 128, SEQ / 128, BATCH * HEADS), 256, QK_SMEM>>>(attnw);
    softmax_kernel<<<BATCH * HEADS * SEQ, 256>>>(attnw);
    pv_mma<<<dim3(SEQ / 128, BATCH * HEADS), 256, PV_SMEM>>>(attnw, out);
}

// round 14
// speedup vs baseline: 1.2458x; 1.1297x over previous
#include <cuda_runtime.h>
#include <cuda_bf16.h>
#include <cstdint>
#include <cstddef>

// Problem constants
#define BATCH 2
#define SEQ   2048
#define EMB   1024
#define HEADS 16
#define HDIM  64
#define NTOK  (BATCH * SEQ)          // 4096
#define KDIM  (EMB * 8)              // 8192 expanded features
#define NB    7                      // spline bases per feature

// ---------------- scratch (static device globals; no allocation) ------------
// Column layout: [0,1024) = x (base part), [1024,8192) = spline bases
// grouped 7 per input feature. W reordered identically.
__device__ uint4 g_phiH4[(size_t)3 * NTOK * KDIM / 8];   // 201 MB  bf16 (x-hi | spline bf16)
__device__ uint4 g_phiL4[(size_t)3 * NTOK * EMB / 8];    // 25 MB   bf16 x-lo only
__device__ uint4 g_WH4[(size_t)3 * EMB * KDIM / 8];      // 50 MB
__device__ uint4 g_WL4[(size_t)3 * EMB * KDIM / 8];      // 50 MB
__device__ __nv_bfloat16 g_qkvH[(size_t)3 * NTOK * EMB];
__device__ __nv_bfloat16 g_qkvL[(size_t)3 * NTOK * EMB];

struct Ptr3 { const float* p[3]; };
struct PtrW { const float* base[3]; const float* spline[3]; const float* scaler[3]; };

// =====================  PTX helpers (compute_103-safe) ======================
__device__ __forceinline__ uint32_t smem_to_u32(const void* p) {
    uint32_t a;
    asm("{ .reg .u64 t; cvta.to.shared.u64 t, %1; cvt.u32.u64 %0, t; }" : "=r"(a) : "l"(p));
    return a;
}
__device__ __forceinline__ void cp_async16(uint32_t dst, const void* src) {
    asm volatile("cp.async.cg.shared.global [%0], [%1], 16;" :: "r"(dst), "l"(src));
}
#define CP_COMMIT() asm volatile("cp.async.commit_group;" ::: "memory")
#define CP_WAIT1()  asm volatile("cp.async.wait_group 1;" ::: "memory")
#define CP_WAIT0()  asm volatile("cp.async.wait_group 0;" ::: "memory")

__device__ __forceinline__ void ldmatrix_x4(uint32_t& r0, uint32_t& r1,
                                            uint32_t& r2, uint32_t& r3, uint32_t addr) {
    asm volatile("ldmatrix.sync.aligned.m8n8.x4.shared.b16 {%0,%1,%2,%3}, [%4];"
                 : "=r"(r0), "=r"(r1), "=r"(r2), "=r"(r3) : "r"(addr));
}
__device__ __forceinline__ void ldmatrix_x4_trans(uint32_t& r0, uint32_t& r1,
                                                  uint32_t& r2, uint32_t& r3, uint32_t addr) {
    asm volatile("ldmatrix.sync.aligned.m8n8.x4.trans.shared.b16 {%0,%1,%2,%3}, [%4];"
                 : "=r"(r0), "=r"(r1), "=r"(r2), "=r"(r3) : "r"(addr));
}
__device__ __forceinline__ void mma_16816(float* d, const uint32_t* a, const uint32_t* b) {
    asm volatile(
        "mma.sync.aligned.m16n8k16.row.col.f32.bf16.bf16.f32 "
        "{%0,%1,%2,%3}, {%4,%5,%6,%7}, {%8,%9}, {%0,%1,%2,%3};"
        : "+f"(d[0]), "+f"(d[1]), "+f"(d[2]), "+f"(d[3])
        : "r"(a[0]), "r"(a[1]), "r"(a[2]), "r"(a[3]), "r"(b[0]), "r"(b[1]));
}
__device__ __forceinline__ void split_bf16(float v, __nv_bfloat16& h, __nv_bfloat16& l) {
    h = __float2bfloat16(v);
    l = __float2bfloat16(v - __bfloat162float(h));
}

// ---------------------------------------------------------------------------
// Kernel 1: expand X -> phi:
//   phiH[n, i]              = hi(x_i)           i in [0,1024)
//   phiL[n, i]              = lo(x_i)           (1024-wide buffer)
//   phiH[n, 1024 + i*7 + j] = bf16(B_j(x_i))    splines single-precision bf16
// ---------------------------------------------------------------------------
__global__ __launch_bounds__(256) void phi_split_all(Ptr3 X) {
    int proj = blockIdx.y;
    int idx = blockIdx.x * blockDim.x + threadIdx.x;   // n*EMB + i
    int n = idx >> 10;
    int i = idx & (EMB - 1);
    float x = X.p[proj][idx];

    float b[10];
#pragma unroll
    for (int t = 0; t < 10; t++) {
        float gt = -2.5f + 0.5f * (float)t;
        b[t] = (x >= gt && x < gt + 0.5f) ? 1.0f : 0.0f;
    }
#pragma unroll
    for (int p = 1; p <= 3; p++) {
#pragma unroll
        for (int t = 0; t < 10; t++) {
            if (t + p < 10) {
                float gt   = -2.5f + 0.5f * (float)t;
                float gtp  = gt + 0.5f * (float)p;
                float gtp1 = gtp + 0.5f;
                float gt1  = gt + 0.5f;
                float left  = (x - gt)   / (gtp - gt);
                float right = (gtp1 - x) / (gtp1 - gt1);
                b[t] = left * b[t] + right * b[t + 1];
            }
        }
    }
    __nv_bfloat16 xh, xl;
    split_bf16(x, xh, xl);
    __nv_bfloat16* PH = (__nv_bfloat16*)g_phiH4 + (size_t)proj * NTOK * KDIM + (size_t)n * KDIM;
    __nv_bfloat16* PL = (__nv_bfloat16*)g_phiL4 + (size_t)proj * NTOK * EMB + (size_t)n * EMB;
    PH[i] = xh;
    PL[i] = xl;
    __nv_bfloat16* SP = PH + 1024 + i * 7;
#pragma unroll
    for (int j = 0; j < NB; j++) SP[j] = __float2bfloat16(b[j]);
}

// ---------------------------------------------------------------------------
// Kernel 2: W[proj][EMB, KDIM], same column layout; hi/lo over ALL columns.
// ---------------------------------------------------------------------------
__global__ __launch_bounds__(256) void wprep_split_all(PtrW Wp) {
    int proj = blockIdx.y;
    int idx = blockIdx.x * blockDim.x + threadIdx.x;   // m*EMB + i
    int i = idx & (EMB - 1);
    int m = idx >> 10;
    size_t mi = (size_t)m * EMB + i;

    __nv_bfloat16* WH = (__nv_bfloat16*)g_WH4 + (size_t)proj * EMB * KDIM + (size_t)m * KDIM;
    __nv_bfloat16* WL = (__nv_bfloat16*)g_WL4 + (size_t)proj * EMB * KDIM + (size_t)m * KDIM;

    __nv_bfloat16 h, l;
    split_bf16(Wp.base[proj][mi], h, l);
    WH[i] = h; WL[i] = l;

    float sc = Wp.scaler[proj][mi];
    const float* sp = Wp.spline[proj] + mi * NB;
#pragma unroll
    for (int j = 0; j < NB; j++) {
        split_bf16(sp[j] * sc, h, l);
        WH[1024 + i * 7 + j] = h;
        WL[1024 + i * 7 + j] = l;
    }
}

// ---------------------------------------------------------------------------
// Kernel 3: mma.sync GEMM  C = phi @ W^T.
// x-region chunks (k0 < 1024): 3-term split (AhBh + AhBl + AlBh).
// spline-region chunks:        2-term (AhBh + AhBl), A single bf16.
// CTA tile 128x256x64, 8 warps, warp tile 64x64, 2-stage cp.async.
// One launch, all 3 projections: grid (4, 32, 3).
// ---------------------------------------------------------------------------
#define BM 128
#define BN 256
#define BK 64
#define NCH (KDIM / BK)                 // 128
#define NXCH (1024 / BK)                // 16 x-region chunks
#define ROWB 144                        // 64 bf16 = 128B + 16B pad
#define A_TILE (BM * ROWB)              // 18432
#define B_TILE (BN * ROWB)              // 36864
#define OFF_AH 0
#define OFF_AL A_TILE
#define OFF_BH (2 * A_TILE)
#define OFF_BL (2 * A_TILE + B_TILE)
#define STAGE (2 * A_TILE + 2 * B_TILE) // 110592
#define GEMM_SMEM (2 * STAGE)           // 221184

__device__ __forceinline__ void load_stage(uint32_t sbase, int k0, bool withAl,
                                           const __nv_bfloat16* pAh, const __nv_bfloat16* pAl,
                                           const __nv_bfloat16* pBh, const __nv_bfloat16* pBl) {
    int t = threadIdx.x;
#pragma unroll
    for (int j = 0; j < 24; j++) {
        int idx = j * 256 + t;          // 0..6143
        const __nv_bfloat16* src;
        uint32_t dst;
        if (idx < 1024) {               // Ah: 128 rows x 8 chunks
            int r = idx >> 3, c = idx & 7;
            src = pAh + (size_t)r * KDIM + k0 + c * 8;
            dst = sbase + OFF_AH + r * ROWB + c * 16;
        } else if (idx < 2048) {        // Al (x-lo, row stride EMB) - only x chunks
            if (!withAl) continue;
            int lq = idx - 1024;
            int r = lq >> 3, c = lq & 7;
            src = pAl + (size_t)r * EMB + k0 + c * 8;
            dst = sbase + OFF_AL + r * ROWB + c * 16;
        } else if (idx < 4096) {        // Bh: 256 rows x 8 chunks
            int lq = idx - 2048;
            int r = lq >> 3, c = lq & 7;
            src = pBh + (size_t)r * KDIM + k0 + c * 8;
            dst = sbase + OFF_BH + r * ROWB + c * 16;
        } else {                        // Bl
            int lq = idx - 4096;
            int r = lq >> 3, c = lq & 7;
            src = pBl + (size_t)r * KDIM + k0 + c * 8;
            dst = sbase + OFF_BL + r * ROWB + c * 16;
        }
        cp_async16(dst, src);
    }
}

__global__ __launch_bounds__(256, 1) void gemm_kan_mma() {
    extern __shared__ char smem[];
    uint32_t sb = smem_to_u32(smem);
    int t = threadIdx.x;
    int lane = t & 31;
    int w = t >> 5;
    int wm = w >> 2;          // 0..1 : 64 m-rows
    int wn = w & 3;           // 0..3 : 64 n-cols

    int which = blockIdx.z;
    int row0 = blockIdx.y * BM;
    int col0 = blockIdx.x * BN;
    const __nv_bfloat16* pAh = (const __nv_bfloat16*)g_phiH4 +
        (size_t)which * NTOK * KDIM + (size_t)row0 * KDIM;
    const __nv_bfloat16* pAl = (const __nv_bfloat16*)g_phiL4 +
        (size_t)which * NTOK * EMB + (size_t)row0 * EMB;
    const __nv_bfloat16* pBh = (const __nv_bfloat16*)g_WH4 +
        (size_t)which * EMB * KDIM + (size_t)col0 * KDIM;
    const __nv_bfloat16* pBl = (const __nv_bfloat16*)g_WL4 +
        (size_t)which * EMB * KDIM + (size_t)col0 * KDIM;

    load_stage(sb + 0 * STAGE, 0 * BK, true, pAh, pAl, pBh, pBl); CP_COMMIT();
    load_stage(sb + 1 * STAGE, 1 * BK, true, pAh, pAl, pBh, pBl); CP_COMMIT();

    float acc[4][8][4];
#pragma unroll
    for (int i = 0; i < 4; i++)
#pragma unroll
        for (int j = 0; j < 8; j++)
#pragma unroll
            for (int q = 0; q < 4; q++) acc[i][j][q] = 0.0f;

    int lr = lane & 15;
    int lh = lane >> 4;
    uint32_t a_off = (uint32_t)((wm * 64 + lr) * ROWB + lh * 16);
    uint32_t b_off = (uint32_t)((wn * 64 + lr) * ROWB + lh * 16);

    for (int c = 0; c < NCH; c++) {
        uint32_t st = sb + (c & 1) * STAGE;
        bool isx = (c < NXCH);
        CP_WAIT1();
        __syncthreads();

#pragma unroll
        for (int ks = 0; ks < 4; ks++) {
            uint32_t koff = ks * 32;
            uint32_t ah[4][4];
#pragma unroll
            for (int i = 0; i < 4; i++)
                ldmatrix_x4(ah[i][0], ah[i][1], ah[i][2], ah[i][3],
                            st + OFF_AH + a_off + i * 16 * ROWB + koff);
            uint32_t bh[4][4], bl[4][4];
#pragma unroll
            for (int p = 0; p < 4; p++) {
                ldmatrix_x4(bh[p][0], bh[p][1], bh[p][2], bh[p][3],
                            st + OFF_BH + b_off + p * 16 * ROWB + koff);
                ldmatrix_x4(bl[p][0], bl[p][1], bl[p][2], bl[p][3],
                            st + OFF_BL + b_off + p * 16 * ROWB + koff);
            }
            // pass 1: Ah * Bh
#pragma unroll
            for (int i = 0; i < 4; i++)
#pragma unroll
                for (int p = 0; p < 4; p++) {
                    uint32_t b0[2] = {bh[p][0], bh[p][2]};
                    uint32_t b1[2] = {bh[p][1], bh[p][3]};
                    mma_16816(acc[i][p * 2 + 0], ah[i], b0);
                    mma_16816(acc[i][p * 2 + 1], ah[i], b1);
                }
            // pass 2: Ah * Bl
#pragma unroll
            for (int i = 0; i < 4; i++)
#pragma unroll
                for (int p = 0; p < 4; p++) {
                    uint32_t b0[2] = {bl[p][0], bl[p][2]};
                    uint32_t b1[2] = {bl[p][1], bl[p][3]};
                    mma_16816(acc[i][p * 2 + 0], ah[i], b0);
                    mma_16816(acc[i][p * 2 + 1], ah[i], b1);
                }
            // pass 3 (x-region only): Al * Bh
            if (isx) {
                uint32_t al[4][4];
#pragma unroll
                for (int i = 0; i < 4; i++)
                    ldmatrix_x4(al[i][0], al[i][1], al[i][2], al[i][3],
                                st + OFF_AL + a_off + i * 16 * ROWB + koff);
#pragma unroll
                for (int i = 0; i < 4; i++)
#pragma unroll
                    for (int p = 0; p < 4; p++) {
                        uint32_t b0[2] = {bh[p][0], bh[p][2]};
                        uint32_t b1[2] = {bh[p][1], bh[p][3]};
                        mma_16816(acc[i][p * 2 + 0], al[i], b0);
                        mma_16816(acc[i][p * 2 + 1], al[i], b1);
                    }
            }
        }
        __syncthreads();
        if (c + 2 < NCH) load_stage(st, (c + 2) * BK, (c + 2) < NXCH, pAh, pAl, pBh, pBl);
        CP_COMMIT();   // empty group when no loads -> wait count stays exact
    }

    // epilogue: split fp32 accumulators to bf16 hi/lo and store
    __nv_bfloat16* CH = g_qkvH + (size_t)which * NTOK * EMB;
    __nv_bfloat16* CL = g_qkvL + (size_t)which * NTOK * EMB;
    int mbase = row0 + wm * 64 + (lane >> 2);
    int nbase = col0 + wn * 64 + (lane & 3) * 2;
#pragma unroll
    for (int i = 0; i < 4; i++) {
#pragma unroll
        for (int j = 0; j < 8; j++) {
            size_t o0 = (size_t)(mbase + i * 16) * EMB + nbase + j * 8;
            size_t o1 = o0 + (size_t)8 * EMB;
            __nv_bfloat162 h2, l2;
            split_bf16(acc[i][j][0], h2.x, l2.x);
            split_bf16(acc[i][j][1], h2.y, l2.y);
            *(uint32_t*)(CH + o0) = *(uint32_t*)&h2;
            *(uint32_t*)(CL + o0) = *(uint32_t*)&l2;
            split_bf16(acc[i][j][2], h2.x, l2.x);
            split_bf16(acc[i][j][3], h2.y, l2.y);
            *(uint32_t*)(CH + o1) = *(uint32_t*)&h2;
            *(uint32_t*)(CL + o1) = *(uint32_t*)&l2;
        }
    }
}

// ---------------------------------------------------------------------------
// Kernel 4: scores via mma, 3-term split. CTA = (bh, 128q, 128k), one-shot.
// ---------------------------------------------------------------------------
#define QK_ROWB 144
#define QK_TILE (128 * QK_ROWB)
#define QK_QH 0
#define QK_QL QK_TILE
#define QK_KH (2 * QK_TILE)
#define QK_KL (3 * QK_TILE)
#define QK_SMEM (4 * QK_TILE)            // 73728

__global__ __launch_bounds__(256, 2) void qk_mma(float* __restrict__ S) {
    extern __shared__ char smem[];
    uint32_t sb = smem_to_u32(smem);
    int t = threadIdx.x;
    int lane = t & 31;
    int w = t >> 5;
    int wm = w >> 1;
    int wn = w & 1;

    int bh = blockIdx.z;
    int b = bh >> 4, h = bh & 15;
    int q0 = blockIdx.y * 128;
    int k0 = blockIdx.x * 128;

    const __nv_bfloat16* QH = g_qkvH + ((size_t)(b * SEQ + q0)) * EMB + h * HDIM;
    const __nv_bfloat16* QL = g_qkvL + ((size_t)(b * SEQ + q0)) * EMB + h * HDIM;
    const __nv_bfloat16* KH = g_qkvH + (size_t)NTOK * EMB + ((size_t)(b * SEQ + k0)) * EMB + h * HDIM;
    const __nv_bfloat16* KL = g_qkvL + (size_t)NTOK * EMB + ((size_t)(b * SEQ + k0)) * EMB + h * HDIM;

    {
        const __nv_bfloat16* srcs[4] = {QH, QL, KH, KL};
        uint32_t dsts[4] = {sb + QK_QH, sb + QK_QL, sb + QK_KH, sb + QK_KL};
#pragma unroll
        for (int j = 0; j < 16; j++) {
            int q = j * 256 + t;
            int op = q >> 10;
            int r = (q >> 3) & 127;
            int c = q & 7;
            cp_async16(dsts[op] + r * QK_ROWB + c * 16,
                       srcs[op] + (size_t)r * EMB + c * 8);
        }
    }
    CP_COMMIT();
    CP_WAIT0();
    __syncthreads();

    float acc[2][8][4];
#pragma unroll
    for (int i = 0; i < 2; i++)
#pragma unroll
        for (int j = 0; j < 8; j++)
#pragma unroll
            for (int q = 0; q < 4; q++) acc[i][j][q] = 0.0f;

    int lr = lane & 15;
    int lh = lane >> 4;
    uint32_t a_off = (uint32_t)((wm * 32 + lr) * QK_ROWB + lh * 16);
    uint32_t b_off = (uint32_t)((wn * 64 + lr) * QK_ROWB + lh * 16);

#pragma unroll
    for (int ks = 0; ks < 4; ks++) {
        uint32_t koff = ks * 32;
        uint32_t ah[2][4], al[2][4];
#pragma unroll
        for (int mi = 0; mi < 2; mi++) {
            ldmatrix_x4(ah[mi][0], ah[mi][1], ah[mi][2], ah[mi][3],
                        sb + QK_QH + a_off + mi * 16 * QK_ROWB + koff);
            ldmatrix_x4(al[mi][0], al[mi][1], al[mi][2], al[mi][3],
                        sb + QK_QL + a_off + mi * 16 * QK_ROWB + koff);
        }
#pragma unroll
        for (int p = 0; p < 4; p++) {
            uint32_t kh[4], kl[4];
            ldmatrix_x4(kh[0], kh[1], kh[2], kh[3],
                        sb + QK_KH + b_off + p * 16 * QK_ROWB + koff);
            ldmatrix_x4(kl[0], kl[1], kl[2], kl[3],
                        sb + QK_KL + b_off + p * 16 * QK_ROWB + koff);
            uint32_t b0h[2] = {kh[0], kh[2]};
            uint32_t b1h[2] = {kh[1], kh[3]};
            uint32_t b0l[2] = {kl[0], kl[2]};
            uint32_t b1l[2] = {kl[1], kl[3]};
#pragma unroll
            for (int mi = 0; mi < 2; mi++) {
                mma_16816(acc[mi][p * 2 + 0], ah[mi], b0h);
                mma_16816(acc[mi][p * 2 + 1], ah[mi], b1h);
            }
#pragma unroll
            for (int mi = 0; mi < 2; mi++) {
                mma_16816(acc[mi][p * 2 + 0], ah[mi], b0l);
                mma_16816(acc[mi][p * 2 + 1], ah[mi], b1l);
            }
#pragma unroll
            for (int mi = 0; mi < 2; mi++) {
                mma_16816(acc[mi][p * 2 + 0], al[mi], b0h);
                mma_16816(acc[mi][p * 2 + 1], al[mi], b1h);
            }
        }
    }

    float* Sb = S + (size_t)bh * SEQ * SEQ;
    const float scale = 0.125f;
#pragma unroll
    for (int mi = 0; mi < 2; mi++) {
        int r0 = q0 + wm * 32 + mi * 16 + (lane >> 2);
#pragma unroll
        for (int n = 0; n < 8; n++) {
            int col = k0 + wn * 64 + n * 8 + (lane & 3) * 2;
            *(float2*)(Sb + (size_t)r0 * SEQ + col) =
                make_float2(acc[mi][n][0] * scale, acc[mi][n][1] * scale);
            *(float2*)(Sb + (size_t)(r0 + 8) * SEQ + col) =
                make_float2(acc[mi][n][2] * scale, acc[mi][n][3] * scale);
        }
    }
}

// ---------------------------------------------------------------------------
// Kernel 5: in-place row softmax (one CTA per row of length SEQ)
// ---------------------------------------------------------------------------
__global__ __launch_bounds__(256) void softmax_kernel(float* __restrict__ W) {
    float* p = W + (size_t)blockIdx.x * SEQ;
    int t = threadIdx.x;
    float4 a = ((float4*)p)[t];
    float4 b = ((float4*)p)[t + 256];

    float m = fmaxf(fmaxf(fmaxf(a.x, a.y), fmaxf(a.z, a.w)),
                    fmaxf(fmaxf(b.x, b.y), fmaxf(b.z, b.w)));
#pragma unroll
    for (int o = 16; o > 0; o >>= 1) m = fmaxf(m, __shfl_xor_sync(0xffffffffu, m, o));

    __shared__ float red_max[8];
    __shared__ float red_sum[8];
    if ((t & 31) == 0) red_max[t >> 5] = m;
    __syncthreads();
    if (t < 32) {
        float v = (t < 8) ? red_max[t] : -3.402823466e38f;
#pragma unroll
        for (int o = 4; o > 0; o >>= 1) v = fmaxf(v, __shfl_xor_sync(0xffffffffu, v, o));
        if (t == 0) red_max[0] = v;
    }
    __syncthreads();
    m = red_max[0];

    a.x = __expf(a.x - m); a.y = __expf(a.y - m); a.z = __expf(a.z - m); a.w = __expf(a.w - m);
    b.x = __expf(b.x - m); b.y = __expf(b.y - m); b.z = __expf(b.z - m); b.w = __expf(b.w - m);
    float s = a.x + a.y + a.z + a.w + b.x + b.y + b.z + b.w;
#pragma unroll
    for (int o = 16; o > 0; o >>= 1) s += __shfl_xor_sync(0xffffffffu, s, o);
    if ((t & 31) == 0) red_sum[t >> 5] = s;
    __syncthreads();
    if (t < 32) {
        float v = (t < 8) ? red_sum[t] : 0.0f;
#pragma unroll
        for (int o = 4; o > 0; o >>= 1) v += __shfl_xor_sync(0xffffffffu, v, o);
        if (t == 0) red_sum[0] = v;
    }
    __syncthreads();
    float inv = 1.0f / red_sum[0];

    a.x *= inv; a.y *= inv; a.z *= inv; a.w *= inv;
    b.x *= inv; b.y *= inv; b.z *= inv; b.w *= inv;
    ((float4*)p)[t] = a;
    ((float4*)p)[t + 256] = b;
}

// ---------------------------------------------------------------------------
// Kernel 6: O = P @ V via mma, 3-term split (PhVh + PhVl + PlVh).
// ---------------------------------------------------------------------------
#define PV_PROWB 272
#define PV_VROWB 144
#define PV_PH 0
#define PV_PL (128 * PV_PROWB)
#define PV_VH (2 * 128 * PV_PROWB)
#define PV_VL (2 * 128 * PV_PROWB + 128 * PV_VROWB)
#define PV_SMEM (2 * 128 * PV_PROWB + 2 * 128 * PV_VROWB)  // 106496

__global__ __launch_bounds__(256, 2) void pv_mma(const float* __restrict__ P,
                                                 float* __restrict__ O) {
    extern __shared__ char smem[];
    uint32_t sb = smem_to_u32(smem);
    int t = threadIdx.x;
    int lane = t & 31;
    int w = t >> 5;
    int wm = w >> 1;
    int wn = w & 1;

    int bh = blockIdx.y;
    int b = bh >> 4, h = bh & 15;
    int q0 = blockIdx.x * 128;
    const float* Pb = P + (size_t)bh * SEQ * SEQ + (size_t)q0 * SEQ;
    const __nv_bfloat16* VH = g_qkvH + (size_t)2 * NTOK * EMB + (size_t)(b * SEQ) * EMB + h * HDIM;
    const __nv_bfloat16* VL = g_qkvL + (size_t)2 * NTOK * EMB + (size_t)(b * SEQ) * EMB + h * HDIM;

    float acc[2][4][4];
#pragma unroll
    for (int i = 0; i < 2; i++)
#pragma unroll
        for (int j = 0; j < 4; j++)
#pragma unroll
            for (int q = 0; q < 4; q++) acc[i][j][q] = 0.0f;

    int lr = lane & 15;
    int lh = lane >> 4;
    uint32_t a_off = (uint32_t)((wm * 32 + lr) * PV_PROWB + lh * 16);
    uint32_t vb_off = (uint32_t)(lr * PV_VROWB + (wn * 32 + lh * 8) * 2);

    for (int kc = 0; kc < SEQ / 128; kc++) {
        if (kc) __syncthreads();
#pragma unroll
        for (int j = 0; j < 8; j++) {
            int q = j * 256 + t;
            int op = q >> 10;
            int r = (q >> 3) & 127;
            int c = q & 7;
            const __nv_bfloat16* src = (op ? VL : VH) + (size_t)(kc * 128 + r) * EMB + c * 8;
            uint32_t dst = sb + (op ? PV_VL : PV_VH) + r * PV_VROWB + c * 16;
            cp_async16(dst, src);
        }
        CP_COMMIT();
#pragma unroll
        for (int j = 0; j < 16; j++) {
            int idx = j * 256 + t;
            int r = idx >> 5;
            int c4 = idx & 31;
            float4 v = *(const float4*)(Pb + (size_t)r * SEQ + kc * 128 + c4 * 4);
            __nv_bfloat162 h01, l01, h23, l23;
            split_bf16(v.x, h01.x, l01.x);
            split_bf16(v.y, h01.y, l01.y);
            split_bf16(v.z, h23.x, l23.x);
            split_bf16(v.w, h23.y, l23.y);
            uint32_t off = (uint32_t)(r * PV_PROWB + c4 * 8);
            *(uint2*)(smem + PV_PH + off) = make_uint2(*(uint32_t*)&h01, *(uint32_t*)&h23);
            *(uint2*)(smem + PV_PL + off) = make_uint2(*(uint32_t*)&l01, *(uint32_t*)&l23);
        }
        CP_WAIT0();
        __syncthreads();

#pragma unroll
        for (int ks = 0; ks < 8; ks++) {
            uint32_t koff = ks * 32;
            uint32_t ph[2][4], pl[2][4];
#pragma unroll
            for (int mi = 0; mi < 2; mi++) {
                ldmatrix_x4(ph[mi][0], ph[mi][1], ph[mi][2], ph[mi][3],
                            sb + PV_PH + a_off + mi * 16 * PV_PROWB + koff);
                ldmatrix_x4(pl[mi][0], pl[mi][1], pl[mi][2], pl[mi][3],
                            sb + PV_PL + a_off + mi * 16 * PV_PROWB + koff);
            }
            uint32_t vrow = (uint32_t)(ks * 16 * PV_VROWB);
            uint32_t vh[2][4], vl[2][4];
#pragma unroll
            for (int g = 0; g < 2; g++) {
                ldmatrix_x4_trans(vh[g][0], vh[g][1], vh[g][2], vh[g][3],
                                  sb + PV_VH + vb_off + vrow + g * 32);
                ldmatrix_x4_trans(vl[g][0], vl[g][1], vl[g][2], vl[g][3],
                                  sb + PV_VL + vb_off + vrow + g * 32);
            }
#pragma unroll
            for (int mi = 0; mi < 2; mi++)
#pragma unroll
                for (int g = 0; g < 2; g++) {
                    uint32_t b0[2] = {vh[g][0], vh[g][1]};
                    uint32_t b1[2] = {vh[g][2], vh[g][3]};
                    mma_16816(acc[mi][g * 2 + 0], ph[mi], b0);
                    mma_16816(acc[mi][g * 2 + 1], ph[mi], b1);
                }
#pragma unroll
            for (int mi = 0; mi < 2; mi++)
#pragma unroll
                for (int g = 0; g < 2; g++) {
                    uint32_t b0[2] = {vl[g][0], vl[g][1]};
                    uint32_t b1[2] = {vl[g][2], vl[g][3]};
                    mma_16816(acc[mi][g * 2 + 0], ph[mi], b0);
                    mma_16816(acc[mi][g * 2 + 1], ph[mi], b1);
                }
#pragma unroll
            for (int mi = 0; mi < 2; mi++)
#pragma unroll
                for (int g = 0; g < 2; g++) {
                    uint32_t b0[2] = {vh[g][0], vh[g][1]};
                    uint32_t b1[2] = {vh[g][2], vh[g][3]};
                    mma_16816(acc[mi][g * 2 + 0], pl[mi], b0);
                    mma_16816(acc[mi][g * 2 + 1], pl[mi], b1);
                }
        }
    }

    float* Ob = O + (size_t)(b * SEQ) * EMB + h * HDIM;
#pragma unroll
    for (int mi = 0; mi < 2; mi++) {
        int r0 = q0 + wm * 32 + mi * 16 + (lane >> 2);
#pragma unroll
        for (int n = 0; n < 4; n++) {
            int col = wn * 32 + n * 8 + (lane & 3) * 2;
            *(float2*)(Ob + (size_t)r0 * EMB + col) =
                make_float2(acc[mi][n][0], acc[mi][n][1]);
            *(float2*)(Ob + (size_t)(r0 + 8) * EMB + col) =
                make_float2(acc[mi][n][2], acc[mi][n][3]);
        }
    }
}

// ---------------------------------------------------------------------------
extern "C" void kernel_launch(void* const* d_in, const int* in_sizes, int n_in,
                              void* d_out, int out_size) {
    (void)in_sizes; (void)n_in; (void)out_size;
    float* out = (float*)d_out;                          // attn_output [B, L, E]
    float* attnw = out + (size_t)NTOK * EMB;             // attn_weights [B, H, L, L]

    Ptr3 X;
    X.p[0] = (const float*)d_in[0];
    X.p[1] = (const float*)d_in[1];
    X.p[2] = (const float*)d_in[2];
    PtrW Wp;
    for (int p = 0; p < 3; p++) {
        Wp.base[p]   = (const float*)d_in[3 + 3 * p];
        Wp.spline[p] = (const float*)d_in[4 + 3 * p];
        Wp.scaler[p] = (const float*)d_in[5 + 3 * p];
    }

    cudaFuncSetAttribute(gemm_kan_mma, cudaFuncAttributeMaxDynamicSharedMemorySize, GEMM_SMEM);
    cudaFuncSetAttribute(qk_mma, cudaFuncAttributeMaxDynamicSharedMemorySize, QK_SMEM);
    cudaFuncSetAttribute(pv_mma, cudaFuncAttributeMaxDynamicSharedMemorySize, PV_SMEM);

    phi_split_all<<<dim3((NTOK * EMB) / 256, 3), 256>>>(X);
    wprep_split_all<<<dim3((EMB * EMB) / 256, 3), 256>>>(Wp);
    gemm_kan_mma<<<dim3(EMB / BN, NTOK / BM, 3), 256, GEMM_SMEM>>>();
    qk_mma<<<dim3(SEQ / 128, SEQ / 128, BATCH * HEADS), 256, QK_SMEM>>>(attnw);
    softmax_kernel<<<BATCH * HEADS * SEQ, 256>>>(attnw);
    pv_mma<<<dim3(SEQ / 128, BATCH * HEADS), 256, PV_SMEM>>>(attnw, out);
}

// round 16
// speedup vs baseline: 1.3039x; 1.0467x over previous
#include <cuda_runtime.h>
#include <cuda_bf16.h>
#include <cstdint>
#include <cstddef>

// Problem constants
#define BATCH 2
#define SEQ   2048
#define EMB   1024
#define HEADS 16
#define HDIM  64
#define NTOK  (BATCH * SEQ)          // 4096
#define KDIM  (EMB * 8)              // 8192 expanded features
#define NB    7                      // spline bases per feature

// ---------------- scratch (static device globals; no allocation) ------------
// Column layout: [0,1024) = x (base part), [1024,8192) = spline bases
// grouped 7 per input feature. W reordered identically.
__device__ uint4 g_phiH4[(size_t)3 * NTOK * KDIM / 8];   // 201 MB  bf16 (x-hi | spline bf16)
__device__ uint4 g_phiL4[(size_t)3 * NTOK * EMB / 8];    // 25 MB   bf16 x-lo only
__device__ uint4 g_WH4[(size_t)3 * EMB * KDIM / 8];      // 50 MB
__device__ uint4 g_WL4[(size_t)3 * EMB * KDIM / 8];      // 50 MB
__device__ __nv_bfloat16 g_qkvH[(size_t)3 * NTOK * EMB];
__device__ __nv_bfloat16 g_qkvL[(size_t)3 * NTOK * EMB];

struct Ptr3 { const float* p[3]; };
struct PtrW { const float* base[3]; const float* spline[3]; const float* scaler[3]; };

// =====================  PTX helpers (compute_103-safe) ======================
__device__ __forceinline__ uint32_t smem_to_u32(const void* p) {
    uint32_t a;
    asm("{ .reg .u64 t; cvta.to.shared.u64 t, %1; cvt.u32.u64 %0, t; }" : "=r"(a) : "l"(p));
    return a;
}
__device__ __forceinline__ void cp_async16(uint32_t dst, const void* src) {
    asm volatile("cp.async.cg.shared.global [%0], [%1], 16;" :: "r"(dst), "l"(src));
}
#define CP_COMMIT() asm volatile("cp.async.commit_group;" ::: "memory")
#define CP_WAIT1()  asm volatile("cp.async.wait_group 1;" ::: "memory")
#define CP_WAIT0()  asm volatile("cp.async.wait_group 0;" ::: "memory")

__device__ __forceinline__ void ldmatrix_x4(uint32_t& r0, uint32_t& r1,
                                            uint32_t& r2, uint32_t& r3, uint32_t addr) {
    asm volatile("ldmatrix.sync.aligned.m8n8.x4.shared.b16 {%0,%1,%2,%3}, [%4];"
                 : "=r"(r0), "=r"(r1), "=r"(r2), "=r"(r3) : "r"(addr));
}
__device__ __forceinline__ void ldmatrix_x4_trans(uint32_t& r0, uint32_t& r1,
                                                  uint32_t& r2, uint32_t& r3, uint32_t addr) {
    asm volatile("ldmatrix.sync.aligned.m8n8.x4.trans.shared.b16 {%0,%1,%2,%3}, [%4];"
                 : "=r"(r0), "=r"(r1), "=r"(r2), "=r"(r3) : "r"(addr));
}
__device__ __forceinline__ void mma_16816(float* d, const uint32_t* a, const uint32_t* b) {
    asm volatile(
        "mma.sync.aligned.m16n8k16.row.col.f32.bf16.bf16.f32 "
        "{%0,%1,%2,%3}, {%4,%5,%6,%7}, {%8,%9}, {%0,%1,%2,%3};"
        : "+f"(d[0]), "+f"(d[1]), "+f"(d[2]), "+f"(d[3])
        : "r"(a[0]), "r"(a[1]), "r"(a[2]), "r"(a[3]), "r"(b[0]), "r"(b[1]));
}
__device__ __forceinline__ void split_bf16(float v, __nv_bfloat16& h, __nv_bfloat16& l) {
    h = __float2bfloat16(v);
    l = __float2bfloat16(v - __bfloat162float(h));
}

// ---------------------------------------------------------------------------
// Kernel 1: expand X -> phi:
//   phiH[n, i]              = hi(x_i)           i in [0,1024)
//   phiL[n, i]              = lo(x_i)           (1024-wide buffer)
//   phiH[n, 1024 + i*7 + j] = bf16(B_j(x_i))    splines single-precision bf16
// ---------------------------------------------------------------------------
__global__ __launch_bounds__(256) void phi_split_all(Ptr3 X) {
    int proj = blockIdx.y;
    int idx = blockIdx.x * blockDim.x + threadIdx.x;   // n*EMB + i
    int n = idx >> 10;
    int i = idx & (EMB - 1);
    float x = X.p[proj][idx];

    float b[10];
#pragma unroll
    for (int t = 0; t < 10; t++) {
        float gt = -2.5f + 0.5f * (float)t;
        b[t] = (x >= gt && x < gt + 0.5f) ? 1.0f : 0.0f;
    }
#pragma unroll
    for (int p = 1; p <= 3; p++) {
#pragma unroll
        for (int t = 0; t < 10; t++) {
            if (t + p < 10) {
                float gt   = -2.5f + 0.5f * (float)t;
                float gtp  = gt + 0.5f * (float)p;
                float gtp1 = gtp + 0.5f;
                float gt1  = gt + 0.5f;
                float left  = (x - gt)   / (gtp - gt);
                float right = (gtp1 - x) / (gtp1 - gt1);
                b[t] = left * b[t] + right * b[t + 1];
            }
        }
    }
    __nv_bfloat16 xh, xl;
    split_bf16(x, xh, xl);
    __nv_bfloat16* PH = (__nv_bfloat16*)g_phiH4 + (size_t)proj * NTOK * KDIM + (size_t)n * KDIM;
    __nv_bfloat16* PL = (__nv_bfloat16*)g_phiL4 + (size_t)proj * NTOK * EMB + (size_t)n * EMB;
    PH[i] = xh;
    PL[i] = xl;
    __nv_bfloat16* SP = PH + 1024 + i * 7;
#pragma unroll
    for (int j = 0; j < NB; j++) SP[j] = __float2bfloat16(b[j]);
}

// ---------------------------------------------------------------------------
// Kernel 2: W[proj][EMB, KDIM], same column layout; hi/lo over ALL columns.
// ---------------------------------------------------------------------------
__global__ __launch_bounds__(256) void wprep_split_all(PtrW Wp) {
    int proj = blockIdx.y;
    int idx = blockIdx.x * blockDim.x + threadIdx.x;   // m*EMB + i
    int i = idx & (EMB - 1);
    int m = idx >> 10;
    size_t mi = (size_t)m * EMB + i;

    __nv_bfloat16* WH = (__nv_bfloat16*)g_WH4 + (size_t)proj * EMB * KDIM + (size_t)m * KDIM;
    __nv_bfloat16* WL = (__nv_bfloat16*)g_WL4 + (size_t)proj * EMB * KDIM + (size_t)m * KDIM;

    __nv_bfloat16 h, l;
    split_bf16(Wp.base[proj][mi], h, l);
    WH[i] = h; WL[i] = l;

    float sc = Wp.scaler[proj][mi];
    const float* sp = Wp.spline[proj] + mi * NB;
#pragma unroll
    for (int j = 0; j < NB; j++) {
        split_bf16(sp[j] * sc, h, l);
        WH[1024 + i * 7 + j] = h;
        WL[1024 + i * 7 + j] = l;
    }
}

// ---------------------------------------------------------------------------
// Kernel 3: mma.sync GEMM  C = phi @ W^T.
// x-region chunks (k0 < 1024): 3-term split (AhBh + AhBl + AlBh).
// spline-region chunks:        2-term (AhBh + AhBl), A single bf16.
// CTA tile 128x256x64, SIXTEEN warps (2x8), warp tile 64x32 ->
// 4 warps/SMSP for latency hiding. 2-stage cp.async.
// One launch, all 3 projections: grid (4, 32, 3).
// ---------------------------------------------------------------------------
#define BM 128
#define BN 256
#define BK 64
#define GTHREADS 512
#define NCH (KDIM / BK)                 // 128
#define NXCH (1024 / BK)                // 16 x-region chunks
#define ROWB 144                        // 64 bf16 = 128B + 16B pad
#define A_TILE (BM * ROWB)              // 18432
#define B_TILE (BN * ROWB)              // 36864
#define OFF_AH 0
#define OFF_AL A_TILE
#define OFF_BH (2 * A_TILE)
#define OFF_BL (2 * A_TILE + B_TILE)
#define STAGE (2 * A_TILE + 2 * B_TILE) // 110592
#define GEMM_SMEM (2 * STAGE)           // 221184

__device__ __forceinline__ void load_stage(uint32_t sbase, int k0, bool isx,
                                           const __nv_bfloat16* pAh, const __nv_bfloat16* pAl,
                                           const __nv_bfloat16* pBh, const __nv_bfloat16* pBl) {
    int t = threadIdx.x;
#pragma unroll
    for (int j = 0; j < 12; j++) {
        int idx = j * GTHREADS + t;     // 0..6143
        const __nv_bfloat16* src;
        uint32_t dst;
        if (idx < 1024) {               // Ah: 128 rows x 8 chunks
            int r = idx >> 3, c = idx & 7;
            src = pAh + (size_t)r * KDIM + k0 + c * 8;
            dst = sbase + OFF_AH + r * ROWB + c * 16;
        } else if (idx < 2048) {        // Al (x-lo, row stride EMB) - x chunks only
            if (!isx) continue;
            int lq = idx - 1024;
            int r = lq >> 3, c = lq & 7;
            src = pAl + (size_t)r * EMB + k0 + c * 8;
            dst = sbase + OFF_AL + r * ROWB + c * 16;
        } else if (idx < 4096) {        // Bh: 256 rows x 8 chunks
            int lq = idx - 2048;
            int r = lq >> 3, c = lq & 7;
            src = pBh + (size_t)r * KDIM + k0 + c * 8;
            dst = sbase + OFF_BH + r * ROWB + c * 16;
        } else {                        // Bl
            int lq = idx - 4096;
            int r = lq >> 3, c = lq & 7;
            src = pBl + (size_t)r * KDIM + k0 + c * 8;
            dst = sbase + OFF_BL + r * ROWB + c * 16;
        }
        cp_async16(dst, src);
    }
}

__global__ __launch_bounds__(GTHREADS, 1) void gemm_kan_mma() {
    extern __shared__ char smem[];
    uint32_t sb = smem_to_u32(smem);
    int t = threadIdx.x;
    int lane = t & 31;
    int w = t >> 5;           // 0..15
    int wm = w >> 3;          // 0..1 : 64 m-rows
    int wn = w & 7;           // 0..7 : 32 n-cols

    int which = blockIdx.z;
    int row0 = blockIdx.y * BM;
    int col0 = blockIdx.x * BN;
    const __nv_bfloat16* pAh = (const __nv_bfloat16*)g_phiH4 +
        (size_t)which * NTOK * KDIM + (size_t)row0 * KDIM;
    const __nv_bfloat16* pAl = (const __nv_bfloat16*)g_phiL4 +
        (size_t)which * NTOK * EMB + (size_t)row0 * EMB;
    const __nv_bfloat16* pBh = (const __nv_bfloat16*)g_WH4 +
        (size_t)which * EMB * KDIM + (size_t)col0 * KDIM;
    const __nv_bfloat16* pBl = (const __nv_bfloat16*)g_WL4 +
        (size_t)which * EMB * KDIM + (size_t)col0 * KDIM;

    load_stage(sb + 0 * STAGE, 0 * BK, true, pAh, pAl, pBh, pBl); CP_COMMIT();
    load_stage(sb + 1 * STAGE, 1 * BK, true, pAh, pAl, pBh, pBl); CP_COMMIT();

    float acc[4][4][4];
#pragma unroll
    for (int i = 0; i < 4; i++)
#pragma unroll
        for (int j = 0; j < 4; j++)
#pragma unroll
            for (int q = 0; q < 4; q++) acc[i][j][q] = 0.0f;

    int lr = lane & 15;
    int lh = lane >> 4;
    uint32_t a_off = (uint32_t)((wm * 64 + lr) * ROWB + lh * 16);
    uint32_t b_off = (uint32_t)((wn * 32 + lr) * ROWB + lh * 16);

    for (int c = 0; c < NCH; c++) {
        uint32_t st = sb + (c & 1) * STAGE;
        bool isx = (c < NXCH);
        CP_WAIT1();
        __syncthreads();

#pragma unroll
        for (int ks = 0; ks < 4; ks++) {
            uint32_t koff = ks * 32;
            uint32_t ah[4][4];
#pragma unroll
            for (int i = 0; i < 4; i++)
                ldmatrix_x4(ah[i][0], ah[i][1], ah[i][2], ah[i][3],
                            st + OFF_AH + a_off + i * 16 * ROWB + koff);
            uint32_t bh[2][4], bl[2][4];
#pragma unroll
            for (int p = 0; p < 2; p++) {
                ldmatrix_x4(bh[p][0], bh[p][1], bh[p][2], bh[p][3],
                            st + OFF_BH + b_off + p * 16 * ROWB + koff);
                ldmatrix_x4(bl[p][0], bl[p][1], bl[p][2], bl[p][3],
                            st + OFF_BL + b_off + p * 16 * ROWB + koff);
            }
            // pass 1: Ah * Bh
#pragma unroll
            for (int i = 0; i < 4; i++)
#pragma unroll
                for (int p = 0; p < 2; p++) {
                    uint32_t b0[2] = {bh[p][0], bh[p][2]};
                    uint32_t b1[2] = {bh[p][1], bh[p][3]};
                    mma_16816(acc[i][p * 2 + 0], ah[i], b0);
                    mma_16816(acc[i][p * 2 + 1], ah[i], b1);
                }
            // pass 2: Ah * Bl
#pragma unroll
            for (int i = 0; i < 4; i++)
#pragma unroll
                for (int p = 0; p < 2; p++) {
                    uint32_t b0[2] = {bl[p][0], bl[p][2]};
                    uint32_t b1[2] = {bl[p][1], bl[p][3]};
                    mma_16816(acc[i][p * 2 + 0], ah[i], b0);
                    mma_16816(acc[i][p * 2 + 1], ah[i], b1);
                }
            // pass 3 (x-region only): Al * Bh
            if (isx) {
                uint32_t al[4][4];
#pragma unroll
                for (int i = 0; i < 4; i++)
                    ldmatrix_x4(al[i][0], al[i][1], al[i][2], al[i][3],
                                st + OFF_AL + a_off + i * 16 * ROWB + koff);
#pragma unroll
                for (int i = 0; i < 4; i++)
#pragma unroll
                    for (int p = 0; p < 2; p++) {
                        uint32_t b0[2] = {bh[p][0], bh[p][2]};
                        uint32_t b1[2] = {bh[p][1], bh[p][3]};
                        mma_16816(acc[i][p * 2 + 0], al[i], b0);
                        mma_16816(acc[i][p * 2 + 1], al[i], b1);
                    }
            }
        }
        __syncthreads();
        if (c + 2 < NCH) load_stage(st, (c + 2) * BK, (c + 2) < NXCH, pAh, pAl, pBh, pBl);
        CP_COMMIT();   // empty group when no loads -> wait count stays exact
    }

    // epilogue: split fp32 accumulators to bf16 hi/lo and store
    __nv_bfloat16* CH = g_qkvH + (size_t)which * NTOK * EMB;
    __nv_bfloat16* CL = g_qkvL + (size_t)which * NTOK * EMB;
    int mbase = row0 + wm * 64 + (lane >> 2);
    int nbase = col0 + wn * 32 + (lane & 3) * 2;
#pragma unroll
    for (int i = 0; i < 4; i++) {
#pragma unroll
        for (int j = 0; j < 4; j++) {
            size_t o0 = (size_t)(mbase + i * 16) * EMB + nbase + j * 8;
            size_t o1 = o0 + (size_t)8 * EMB;
            __nv_bfloat162 h2, l2;
            split_bf16(acc[i][j][0], h2.x, l2.x);
            split_bf16(acc[i][j][1], h2.y, l2.y);
            *(uint32_t*)(CH + o0) = *(uint32_t*)&h2;
            *(uint32_t*)(CL + o0) = *(uint32_t*)&l2;
            split_bf16(acc[i][j][2], h2.x, l2.x);
            split_bf16(acc[i][j][3], h2.y, l2.y);
            *(uint32_t*)(CH + o1) = *(uint32_t*)&h2;
            *(uint32_t*)(CL + o1) = *(uint32_t*)&l2;
        }
    }
}

// ---------------------------------------------------------------------------
// Kernel 4: scores via mma, 3-term split. CTA = (bh, 128q, 128k), one-shot.
// ---------------------------------------------------------------------------
#define QK_ROWB 144
#define QK_TILE (128 * QK_ROWB)
#define QK_QH 0
#define QK_QL QK_TILE
#define QK_KH (2 * QK_TILE)
#define QK_KL (3 * QK_TILE)
#define QK_SMEM (4 * QK_TILE)            // 73728

__global__ __launch_bounds__(256, 2) void qk_mma(float* __restrict__ S) {
    extern __shared__ char smem[];
    uint32_t sb = smem_to_u32(smem);
    int t = threadIdx.x;
    int lane = t & 31;
    int w = t >> 5;
    int wm = w >> 1;
    int wn = w & 1;

    int bh = blockIdx.z;
    int b = bh >> 4, h = bh & 15;
    int q0 = blockIdx.y * 128;
    int k0 = blockIdx.x * 128;

    const __nv_bfloat16* QH = g_qkvH + ((size_t)(b * SEQ + q0)) * EMB + h * HDIM;
    const __nv_bfloat16* QL = g_qkvL + ((size_t)(b * SEQ + q0)) * EMB + h * HDIM;
    const __nv_bfloat16* KH = g_qkvH + (size_t)NTOK * EMB + ((size_t)(b * SEQ + k0)) * EMB + h * HDIM;
    const __nv_bfloat16* KL = g_qkvL + (size_t)NTOK * EMB + ((size_t)(b * SEQ + k0)) * EMB + h * HDIM;

    {
        const __nv_bfloat16* srcs[4] = {QH, QL, KH, KL};
        uint32_t dsts[4] = {sb + QK_QH, sb + QK_QL, sb + QK_KH, sb + QK_KL};
#pragma unroll
        for (int j = 0; j < 16; j++) {
            int q = j * 256 + t;
            int op = q >> 10;
            int r = (q >> 3) & 127;
            int c = q & 7;
            cp_async16(dsts[op] + r * QK_ROWB + c * 16,
                       srcs[op] + (size_t)r * EMB + c * 8);
        }
    }
    CP_COMMIT();
    CP_WAIT0();
    __syncthreads();

    float acc[2][8][4];
#pragma unroll
    for (int i = 0; i < 2; i++)
#pragma unroll
        for (int j = 0; j < 8; j++)
#pragma unroll
            for (int q = 0; q < 4; q++) acc[i][j][q] = 0.0f;

    int lr = lane & 15;
    int lh = lane >> 4;
    uint32_t a_off = (uint32_t)((wm * 32 + lr) * QK_ROWB + lh * 16);
    uint32_t b_off = (uint32_t)((wn * 64 + lr) * QK_ROWB + lh * 16);

#pragma unroll
    for (int ks = 0; ks < 4; ks++) {
        uint32_t koff = ks * 32;
        uint32_t ah[2][4], al[2][4];
#pragma unroll
        for (int mi = 0; mi < 2; mi++) {
            ldmatrix_x4(ah[mi][0], ah[mi][1], ah[mi][2], ah[mi][3],
                        sb + QK_QH + a_off + mi * 16 * QK_ROWB + koff);
            ldmatrix_x4(al[mi][0], al[mi][1], al[mi][2], al[mi][3],
                        sb + QK_QL + a_off + mi * 16 * QK_ROWB + koff);
        }
#pragma unroll
        for (int p = 0; p < 4; p++) {
            uint32_t kh[4], kl[4];
            ldmatrix_x4(kh[0], kh[1], kh[2], kh[3],
                        sb + QK_KH + b_off + p * 16 * QK_ROWB + koff);
            ldmatrix_x4(kl[0], kl[1], kl[2], kl[3],
                        sb + QK_KL + b_off + p * 16 * QK_ROWB + koff);
            uint32_t b0h[2] = {kh[0], kh[2]};
            uint32_t b1h[2] = {kh[1], kh[3]};
            uint32_t b0l[2] = {kl[0], kl[2]};
            uint32_t b1l[2] = {kl[1], kl[3]};
#pragma unroll
            for (int mi = 0; mi < 2; mi++) {
                mma_16816(acc[mi][p * 2 + 0], ah[mi], b0h);
                mma_16816(acc[mi][p * 2 + 1], ah[mi], b1h);
            }
#pragma unroll
            for (int mi = 0; mi < 2; mi++) {
                mma_16816(acc[mi][p * 2 + 0], ah[mi], b0l);
                mma_16816(acc[mi][p * 2 + 1], ah[mi], b1l);
            }
#pragma unroll
            for (int mi = 0; mi < 2; mi++) {
                mma_16816(acc[mi][p * 2 + 0], al[mi], b0h);
                mma_16816(acc[mi][p * 2 + 1], al[mi], b1h);
            }
        }
    }

    float* Sb = S + (size_t)bh * SEQ * SEQ;
    const float scale = 0.125f;
#pragma unroll
    for (int mi = 0; mi < 2; mi++) {
        int r0 = q0 + wm * 32 + mi * 16 + (lane >> 2);
#pragma unroll
        for (int n = 0; n < 8; n++) {
            int col = k0 + wn * 64 + n * 8 + (lane & 3) * 2;
            *(float2*)(Sb + (size_t)r0 * SEQ + col) =
                make_float2(acc[mi][n][0] * scale, acc[mi][n][1] * scale);
            *(float2*)(Sb + (size_t)(r0 + 8) * SEQ + col) =
                make_float2(acc[mi][n][2] * scale, acc[mi][n][3] * scale);
        }
    }
}

// ---------------------------------------------------------------------------
// Kernel 5: in-place row softmax (one CTA per row of length SEQ)
// ---------------------------------------------------------------------------
__global__ __launch_bounds__(256) void softmax_kernel(float* __restrict__ W) {
    float* p = W + (size_t)blockIdx.x * SEQ;
    int t = threadIdx.x;
    float4 a = ((float4*)p)[t];
    float4 b = ((float4*)p)[t + 256];

    float m = fmaxf(fmaxf(fmaxf(a.x, a.y), fmaxf(a.z, a.w)),
                    fmaxf(fmaxf(b.x, b.y), fmaxf(b.z, b.w)));
#pragma unroll
    for (int o = 16; o > 0; o >>= 1) m = fmaxf(m, __shfl_xor_sync(0xffffffffu, m, o));

    __shared__ float red_max[8];
    __shared__ float red_sum[8];
    if ((t & 31) == 0) red_max[t >> 5] = m;
    __syncthreads();
    if (t < 32) {
        float v = (t < 8) ? red_max[t] : -3.402823466e38f;
#pragma unroll
        for (int o = 4; o > 0; o >>= 1) v = fmaxf(v, __shfl_xor_sync(0xffffffffu, v, o));
        if (t == 0) red_max[0] = v;
    }
    __syncthreads();
    m = red_max[0];

    a.x = __expf(a.x - m); a.y = __expf(a.y - m); a.z = __expf(a.z - m); a.w = __expf(a.w - m);
    b.x = __expf(b.x - m); b.y = __expf(b.y - m); b.z = __expf(b.z - m); b.w = __expf(b.w - m);
    float s = a.x + a.y + a.z + a.w + b.x + b.y + b.z + b.w;
#pragma unroll
    for (int o = 16; o > 0; o >>= 1) s += __shfl_xor_sync(0xffffffffu, s, o);
    if ((t & 31) == 0) red_sum[t >> 5] = s;
    __syncthreads();
    if (t < 32) {
        float v = (t < 8) ? red_sum[t] : 0.0f;
#pragma unroll
        for (int o = 4; o > 0; o >>= 1) v += __shfl_xor_sync(0xffffffffu, v, o);
        if (t == 0) red_sum[0] = v;
    }
    __syncthreads();
    float inv = 1.0f / red_sum[0];

    a.x *= inv; a.y *= inv; a.z *= inv; a.w *= inv;
    b.x *= inv; b.y *= inv; b.z *= inv; b.w *= inv;
    ((float4*)p)[t] = a;
    ((float4*)p)[t + 256] = b;
}

// ---------------------------------------------------------------------------
// Kernel 6: O = P @ V via mma, 3-term split (PhVh + PhVl + PlVh).
// ---------------------------------------------------------------------------
#define PV_PROWB 272
#define PV_VROWB 144
#define PV_PH 0
#define PV_PL (128 * PV_PROWB)
#define PV_VH (2 * 128 * PV_PROWB)
#define PV_VL (2 * 128 * PV_PROWB + 128 * PV_VROWB)
#define PV_SMEM (2 * 128 * PV_PROWB + 2 * 128 * PV_VROWB)  // 106496

__global__ __launch_bounds__(256, 2) void pv_mma(const float* __restrict__ P,
                                                 float* __restrict__ O) {
    extern __shared__ char smem[];
    uint32_t sb = smem_to_u32(smem);
    int t = threadIdx.x;
    int lane = t & 31;
    int w = t >> 5;
    int wm = w >> 1;
    int wn = w & 1;

    int bh = blockIdx.y;
    int b = bh >> 4, h = bh & 15;
    int q0 = blockIdx.x * 128;
    const float* Pb = P + (size_t)bh * SEQ * SEQ + (size_t)q0 * SEQ;
    const __nv_bfloat16* VH = g_qkvH + (size_t)2 * NTOK * EMB + (size_t)(b * SEQ) * EMB + h * HDIM;
    const __nv_bfloat16* VL = g_qkvL + (size_t)2 * NTOK * EMB + (size_t)(b * SEQ) * EMB + h * HDIM;

    float acc[2][4][4];
#pragma unroll
    for (int i = 0; i < 2; i++)
#pragma unroll
        for (int j = 0; j < 4; j++)
#pragma unroll
            for (int q = 0; q < 4; q++) acc[i][j][q] = 0.0f;

    int lr = lane & 15;
    int lh = lane >> 4;
    uint32_t a_off = (uint32_t)((wm * 32 + lr) * PV_PROWB + lh * 16);
    uint32_t vb_off = (uint32_t)(lr * PV_VROWB + (wn * 32 + lh * 8) * 2);

    for (int kc = 0; kc < SEQ / 128; kc++) {
        if (kc) __syncthreads();
#pragma unroll
        for (int j = 0; j < 8; j++) {
            int q = j * 256 + t;
            int op = q >> 10;
            int r = (q >> 3) & 127;
            int c = q & 7;
            const __nv_bfloat16* src = (op ? VL : VH) + (size_t)(kc * 128 + r) * EMB + c * 8;
            uint32_t dst = sb + (op ? PV_VL : PV_VH) + r * PV_VROWB + c * 16;
            cp_async16(dst, src);
        }
        CP_COMMIT();
#pragma unroll
        for (int j = 0; j < 16; j++) {
            int idx = j * 256 + t;
            int r = idx >> 5;
            int c4 = idx & 31;
            float4 v = *(const float4*)(Pb + (size_t)r * SEQ + kc * 128 + c4 * 4);
            __nv_bfloat162 h01, l01, h23, l23;
            split_bf16(v.x, h01.x, l01.x);
            split_bf16(v.y, h01.y, l01.y);
            split_bf16(v.z, h23.x, l23.x);
            split_bf16(v.w, h23.y, l23.y);
            uint32_t off = (uint32_t)(r * PV_PROWB + c4 * 8);
            *(uint2*)(smem + PV_PH + off) = make_uint2(*(uint32_t*)&h01, *(uint32_t*)&h23);
            *(uint2*)(smem + PV_PL + off) = make_uint2(*(uint32_t*)&l01, *(uint32_t*)&l23);
        }
        CP_WAIT0();
        __syncthreads();

#pragma unroll
        for (int ks = 0; ks < 8; ks++) {
            uint32_t koff = ks * 32;
            uint32_t ph[2][4], pl[2][4];
#pragma unroll
            for (int mi = 0; mi < 2; mi++) {
                ldmatrix_x4(ph[mi][0], ph[mi][1], ph[mi][2], ph[mi][3],
                            sb + PV_PH + a_off + mi * 16 * PV_PROWB + koff);
                ldmatrix_x4(pl[mi][0], pl[mi][1], pl[mi][2], pl[mi][3],
                            sb + PV_PL + a_off + mi * 16 * PV_PROWB + koff);
            }
            uint32_t vrow = (uint32_t)(ks * 16 * PV_VROWB);
            uint32_t vh[2][4], vl[2][4];
#pragma unroll
            for (int g = 0; g < 2; g++) {
                ldmatrix_x4_trans(vh[g][0], vh[g][1], vh[g][2], vh[g][3],
                                  sb + PV_VH + vb_off + vrow + g * 32);
                ldmatrix_x4_trans(vl[g][0], vl[g][1], vl[g][2], vl[g][3],
                                  sb + PV_VL + vb_off + vrow + g * 32);
            }
#pragma unroll
            for (int mi = 0; mi < 2; mi++)
#pragma unroll
                for (int g = 0; g < 2; g++) {
                    uint32_t b0[2] = {vh[g][0], vh[g][1]};
                    uint32_t b1[2] = {vh[g][2], vh[g][3]};
                    mma_16816(acc[mi][g * 2 + 0], ph[mi], b0);
                    mma_16816(acc[mi][g * 2 + 1], ph[mi], b1);
                }
#pragma unroll
            for (int mi = 0; mi < 2; mi++)
#pragma unroll
                for (int g = 0; g < 2; g++) {
                    uint32_t b0[2] = {vl[g][0], vl[g][1]};
                    uint32_t b1[2] = {vl[g][2], vl[g][3]};
                    mma_16816(acc[mi][g * 2 + 0], ph[mi], b0);
                    mma_16816(acc[mi][g * 2 + 1], ph[mi], b1);
                }
#pragma unroll
            for (int mi = 0; mi < 2; mi++)
#pragma unroll
                for (int g = 0; g < 2; g++) {
                    uint32_t b0[2] = {vh[g][0], vh[g][1]};
                    uint32_t b1[2] = {vh[g][2], vh[g][3]};
                    mma_16816(acc[mi][g * 2 + 0], pl[mi], b0);
                    mma_16816(acc[mi][g * 2 + 1], pl[mi], b1);
                }
        }
    }

    float* Ob = O + (size_t)(b * SEQ) * EMB + h * HDIM;
#pragma unroll
    for (int mi = 0; mi < 2; mi++) {
        int r0 = q0 + wm * 32 + mi * 16 + (lane >> 2);
#pragma unroll
        for (int n = 0; n < 4; n++) {
            int col = wn * 32 + n * 8 + (lane & 3) * 2;
            *(float2*)(Ob + (size_t)r0 * EMB + col) =
                make_float2(acc[mi][n][0], acc[mi][n][1]);
            *(float2*)(Ob + (size_t)(r0 + 8) * EMB + col) =
                make_float2(acc[mi][n][2], acc[mi][n][3]);
        }
    }
}

// ---------------------------------------------------------------------------
extern "C" void kernel_launch(void* const* d_in, const int* in_sizes, int n_in,
                              void* d_out, int out_size) {
    (void)in_sizes; (void)n_in; (void)out_size;
    float* out = (float*)d_out;                          // attn_output [B, L, E]
    float* attnw = out + (size_t)NTOK * EMB;             // attn_weights [B, H, L, L]

    Ptr3 X;
    X.p[0] = (const float*)d_in[0];
    X.p[1] = (const float*)d_in[1];
    X.p[2] = (const float*)d_in[2];
    PtrW Wp;
    for (int p = 0; p < 3; p++) {
        Wp.base[p]   = (const float*)d_in[3 + 3 * p];
        Wp.spline[p] = (const float*)d_in[4 + 3 * p];
        Wp.scaler[p] = (const float*)d_in[5 + 3 * p];
    }

    cudaFuncSetAttribute(gemm_kan_mma, cudaFuncAttributeMaxDynamicSharedMemorySize, GEMM_SMEM);
    cudaFuncSetAttribute(qk_mma, cudaFuncAttributeMaxDynamicSharedMemorySize, QK_SMEM);
    cudaFuncSetAttribute(pv_mma, cudaFuncAttributeMaxDynamicSharedMemorySize, PV_SMEM);

    phi_split_all<<<dim3((NTOK * EMB) / 256, 3), 256>>>(X);
    wprep_split_all<<<dim3((EMB * EMB) / 256, 3), 256>>>(Wp);
    gemm_kan_mma<<<dim3(EMB / BN, NTOK / BM, 3), GTHREADS, GEMM_SMEM>>>();
    qk_mma<<<dim3(SEQ / 128, SEQ / 128, BATCH * HEADS), 256, QK_SMEM>>>(attnw);
    softmax_kernel<<<BATCH * HEADS * SEQ, 256>>>(attnw);
    pv_mma<<<dim3(SEQ / 128, BATCH * HEADS), 256, PV_SMEM>>>(attnw, out);
}

// round 17
// speedup vs baseline: 1.6964x; 1.3010x over previous
#include <cuda_runtime.h>
#include <cuda_bf16.h>
#include <cuda_fp16.h>
#include <cstdint>
#include <cstddef>

// Problem constants
#define BATCH 2
#define SEQ   2048
#define EMB   1024
#define HEADS 16
#define HDIM  64
#define NTOK  (BATCH * SEQ)          // 4096
#define KDIM  (EMB * 8)              // 8192 expanded features
#define NB    7                      // spline bases per feature

// ---------------- scratch (static device globals; no allocation) ------------
// Column layout: [0,1024) = x (base part, bf16 hi/lo split),
// [1024,8192) = spline bases grouped 7 per input feature, stored as FP16
// (single precision term). W reordered identically (x: bf16 hi/lo, spline: fp16).
__device__ uint4 g_phiH4[(size_t)3 * NTOK * KDIM / 8];   // 201 MB
__device__ uint4 g_phiL4[(size_t)3 * NTOK * EMB / 8];    // 25 MB   bf16 x-lo only
__device__ uint4 g_WH4[(size_t)3 * EMB * KDIM / 8];      // 50 MB
__device__ uint4 g_WL4[(size_t)3 * EMB * KDIM / 8];      // 50 MB (x region used)
__device__ __nv_bfloat16 g_qkvH[(size_t)3 * NTOK * EMB];
__device__ __nv_bfloat16 g_qkvL[(size_t)3 * NTOK * EMB];

struct Ptr3 { const float* p[3]; };
struct PtrW { const float* base[3]; const float* spline[3]; const float* scaler[3]; };

// =====================  PTX helpers (compute_103-safe) ======================
__device__ __forceinline__ uint32_t smem_to_u32(const void* p) {
    uint32_t a;
    asm("{ .reg .u64 t; cvta.to.shared.u64 t, %1; cvt.u32.u64 %0, t; }" : "=r"(a) : "l"(p));
    return a;
}
__device__ __forceinline__ void cp_async16(uint32_t dst, const void* src) {
    asm volatile("cp.async.cg.shared.global [%0], [%1], 16;" :: "r"(dst), "l"(src));
}
#define CP_COMMIT() asm volatile("cp.async.commit_group;" ::: "memory")
#define CP_WAIT1()  asm volatile("cp.async.wait_group 1;" ::: "memory")
#define CP_WAIT0()  asm volatile("cp.async.wait_group 0;" ::: "memory")

__device__ __forceinline__ void ldmatrix_x4(uint32_t& r0, uint32_t& r1,
                                            uint32_t& r2, uint32_t& r3, uint32_t addr) {
    asm volatile("ldmatrix.sync.aligned.m8n8.x4.shared.b16 {%0,%1,%2,%3}, [%4];"
                 : "=r"(r0), "=r"(r1), "=r"(r2), "=r"(r3) : "r"(addr));
}
__device__ __forceinline__ void ldmatrix_x4_trans(uint32_t& r0, uint32_t& r1,
                                                  uint32_t& r2, uint32_t& r3, uint32_t addr) {
    asm volatile("ldmatrix.sync.aligned.m8n8.x4.trans.shared.b16 {%0,%1,%2,%3}, [%4];"
                 : "=r"(r0), "=r"(r1), "=r"(r2), "=r"(r3) : "r"(addr));
}
// D (fp32) += A(bf16) @ B(bf16)^T
__device__ __forceinline__ void mma_16816(float* d, const uint32_t* a, const uint32_t* b) {
    asm volatile(
        "mma.sync.aligned.m16n8k16.row.col.f32.bf16.bf16.f32 "
        "{%0,%1,%2,%3}, {%4,%5,%6,%7}, {%8,%9}, {%0,%1,%2,%3};"
        : "+f"(d[0]), "+f"(d[1]), "+f"(d[2]), "+f"(d[3])
        : "r"(a[0]), "r"(a[1]), "r"(a[2]), "r"(a[3]), "r"(b[0]), "r"(b[1]));
}
// D (fp32) += A(fp16) @ B(fp16)^T
__device__ __forceinline__ void mma_16816_f16(float* d, const uint32_t* a, const uint32_t* b) {
    asm volatile(
        "mma.sync.aligned.m16n8k16.row.col.f32.f16.f16.f32 "
        "{%0,%1,%2,%3}, {%4,%5,%6,%7}, {%8,%9}, {%0,%1,%2,%3};"
        : "+f"(d[0]), "+f"(d[1]), "+f"(d[2]), "+f"(d[3])
        : "r"(a[0]), "r"(a[1]), "r"(a[2]), "r"(a[3]), "r"(b[0]), "r"(b[1]));
}
__device__ __forceinline__ void split_bf16(float v, __nv_bfloat16& h, __nv_bfloat16& l) {
    h = __float2bfloat16(v);
    l = __float2bfloat16(v - __bfloat162float(h));
}

// ---------------------------------------------------------------------------
// Kernel 1: expand X -> phi:
//   phiH[n, i]              = bf16-hi(x_i)      i in [0,1024)
//   phiL[n, i]              = bf16-lo(x_i)
//   phiH[n, 1024 + i*7 + j] = fp16(B_j(x_i))    splines single fp16
// ---------------------------------------------------------------------------
__global__ __launch_bounds__(256) void phi_split_all(Ptr3 X) {
    int proj = blockIdx.y;
    int idx = blockIdx.x * blockDim.x + threadIdx.x;   // n*EMB + i
    int n = idx >> 10;
    int i = idx & (EMB - 1);
    float x = X.p[proj][idx];

    float b[10];
#pragma unroll
    for (int t = 0; t < 10; t++) {
        float gt = -2.5f + 0.5f * (float)t;
        b[t] = (x >= gt && x < gt + 0.5f) ? 1.0f : 0.0f;
    }
#pragma unroll
    for (int p = 1; p <= 3; p++) {
#pragma unroll
        for (int t = 0; t < 10; t++) {
            if (t + p < 10) {
                float gt   = -2.5f + 0.5f * (float)t;
                float gtp  = gt + 0.5f * (float)p;
                float gtp1 = gtp + 0.5f;
                float gt1  = gt + 0.5f;
                float left  = (x - gt)   / (gtp - gt);
                float right = (gtp1 - x) / (gtp1 - gt1);
                b[t] = left * b[t] + right * b[t + 1];
            }
        }
    }
    __nv_bfloat16 xh, xl;
    split_bf16(x, xh, xl);
    __nv_bfloat16* PH = (__nv_bfloat16*)g_phiH4 + (size_t)proj * NTOK * KDIM + (size_t)n * KDIM;
    __nv_bfloat16* PL = (__nv_bfloat16*)g_phiL4 + (size_t)proj * NTOK * EMB + (size_t)n * EMB;
    PH[i] = xh;
    PL[i] = xl;
    __half* SP = (__half*)(PH + 1024) + i * 7;
#pragma unroll
    for (int j = 0; j < NB; j++) SP[j] = __float2half(b[j]);
}

// ---------------------------------------------------------------------------
// Kernel 2: W[proj][EMB, KDIM]: x cols bf16 hi/lo; spline cols fp16 single.
// ---------------------------------------------------------------------------
__global__ __launch_bounds__(256) void wprep_split_all(PtrW Wp) {
    int proj = blockIdx.y;
    int idx = blockIdx.x * blockDim.x + threadIdx.x;   // m*EMB + i
    int i = idx & (EMB - 1);
    int m = idx >> 10;
    size_t mi = (size_t)m * EMB + i;

    __nv_bfloat16* WH = (__nv_bfloat16*)g_WH4 + (size_t)proj * EMB * KDIM + (size_t)m * KDIM;
    __nv_bfloat16* WL = (__nv_bfloat16*)g_WL4 + (size_t)proj * EMB * KDIM + (size_t)m * KDIM;

    __nv_bfloat16 h, l;
    split_bf16(Wp.base[proj][mi], h, l);
    WH[i] = h; WL[i] = l;

    float sc = Wp.scaler[proj][mi];
    const float* sp = Wp.spline[proj] + mi * NB;
    __half* WS = (__half*)(WH + 1024) + i * 7;
#pragma unroll
    for (int j = 0; j < NB; j++) WS[j] = __float2half(sp[j] * sc);
}

// ---------------------------------------------------------------------------
// Kernel 3: mma.sync GEMM  C = phi @ W^T.
// x-region chunks (k0 < 1024): 3-term bf16 split (AhBh + AhBl + AlBh).
// spline-region chunks:        1-term fp16 (A fp16, W fp16).
// CTA tile 128x256x64, 16 warps (2x8), warp tile 64x32, 2-stage cp.async.
// One launch, all 3 projections: grid (4, 32, 3).
// ---------------------------------------------------------------------------
#define BM 128
#define BN 256
#define BK 64
#define GTHREADS 512
#define NCH (KDIM / BK)                 // 128
#define NXCH (1024 / BK)                // 16 x-region chunks
#define ROWB 144                        // 64 elems = 128B + 16B pad
#define A_TILE (BM * ROWB)              // 18432
#define B_TILE (BN * ROWB)              // 36864
#define OFF_AH 0
#define OFF_AL A_TILE
#define OFF_BH (2 * A_TILE)
#define OFF_BL (2 * A_TILE + B_TILE)
#define STAGE (2 * A_TILE + 2 * B_TILE) // 110592
#define GEMM_SMEM (2 * STAGE)           // 221184

__device__ __forceinline__ void load_stage(uint32_t sbase, int k0, bool isx,
                                           const __nv_bfloat16* pAh, const __nv_bfloat16* pAl,
                                           const __nv_bfloat16* pBh, const __nv_bfloat16* pBl) {
    int t = threadIdx.x;
#pragma unroll
    for (int j = 0; j < 12; j++) {
        int idx = j * GTHREADS + t;     // 0..6143
        const __nv_bfloat16* src;
        uint32_t dst;
        if (idx < 1024) {               // A (hi / fp16 spline): 128 rows x 8 chunks
            int r = idx >> 3, c = idx & 7;
            src = pAh + (size_t)r * KDIM + k0 + c * 8;
            dst = sbase + OFF_AH + r * ROWB + c * 16;
        } else if (idx < 2048) {        // Al (x-lo, row stride EMB) - x chunks only
            if (!isx) continue;
            int lq = idx - 1024;
            int r = lq >> 3, c = lq & 7;
            src = pAl + (size_t)r * EMB + k0 + c * 8;
            dst = sbase + OFF_AL + r * ROWB + c * 16;
        } else if (idx < 4096) {        // B (hi / fp16 spline): 256 rows x 8 chunks
            int lq = idx - 2048;
            int r = lq >> 3, c = lq & 7;
            src = pBh + (size_t)r * KDIM + k0 + c * 8;
            dst = sbase + OFF_BH + r * ROWB + c * 16;
        } else {                        // Bl - x chunks only
            if (!isx) continue;
            int lq = idx - 4096;
            int r = lq >> 3, c = lq & 7;
            src = pBl + (size_t)r * KDIM + k0 + c * 8;
            dst = sbase + OFF_BL + r * ROWB + c * 16;
        }
        cp_async16(dst, src);
    }
}

__global__ __launch_bounds__(GTHREADS, 1) void gemm_kan_mma() {
    extern __shared__ char smem[];
    uint32_t sb = smem_to_u32(smem);
    int t = threadIdx.x;
    int lane = t & 31;
    int w = t >> 5;           // 0..15
    int wm = w >> 3;          // 0..1 : 64 m-rows
    int wn = w & 7;           // 0..7 : 32 n-cols

    int which = blockIdx.z;
    int row0 = blockIdx.y * BM;
    int col0 = blockIdx.x * BN;
    const __nv_bfloat16* pAh = (const __nv_bfloat16*)g_phiH4 +
        (size_t)which * NTOK * KDIM + (size_t)row0 * KDIM;
    const __nv_bfloat16* pAl = (const __nv_bfloat16*)g_phiL4 +
        (size_t)which * NTOK * EMB + (size_t)row0 * EMB;
    const __nv_bfloat16* pBh = (const __nv_bfloat16*)g_WH4 +
        (size_t)which * EMB * KDIM + (size_t)col0 * KDIM;
    const __nv_bfloat16* pBl = (const __nv_bfloat16*)g_WL4 +
        (size_t)which * EMB * KDIM + (size_t)col0 * KDIM;

    load_stage(sb + 0 * STAGE, 0 * BK, true, pAh, pAl, pBh, pBl); CP_COMMIT();
    load_stage(sb + 1 * STAGE, 1 * BK, true, pAh, pAl, pBh, pBl); CP_COMMIT();

    float acc[4][4][4];
#pragma unroll
    for (int i = 0; i < 4; i++)
#pragma unroll
        for (int j = 0; j < 4; j++)
#pragma unroll
            for (int q = 0; q < 4; q++) acc[i][j][q] = 0.0f;

    int lr = lane & 15;
    int lh = lane >> 4;
    uint32_t a_off = (uint32_t)((wm * 64 + lr) * ROWB + lh * 16);
    uint32_t b_off = (uint32_t)((wn * 32 + lr) * ROWB + lh * 16);

    for (int c = 0; c < NCH; c++) {
        uint32_t st = sb + (c & 1) * STAGE;
        bool isx = (c < NXCH);
        CP_WAIT1();
        __syncthreads();

#pragma unroll
        for (int ks = 0; ks < 4; ks++) {
            uint32_t koff = ks * 32;
            uint32_t ah[4][4];
#pragma unroll
            for (int i = 0; i < 4; i++)
                ldmatrix_x4(ah[i][0], ah[i][1], ah[i][2], ah[i][3],
                            st + OFF_AH + a_off + i * 16 * ROWB + koff);
            uint32_t bh[2][4];
#pragma unroll
            for (int p = 0; p < 2; p++)
                ldmatrix_x4(bh[p][0], bh[p][1], bh[p][2], bh[p][3],
                            st + OFF_BH + b_off + p * 16 * ROWB + koff);

            if (!isx) {
                // spline region: single fp16 term
#pragma unroll
                for (int i = 0; i < 4; i++)
#pragma unroll
                    for (int p = 0; p < 2; p++) {
                        uint32_t b0[2] = {bh[p][0], bh[p][2]};
                        uint32_t b1[2] = {bh[p][1], bh[p][3]};
                        mma_16816_f16(acc[i][p * 2 + 0], ah[i], b0);
                        mma_16816_f16(acc[i][p * 2 + 1], ah[i], b1);
                    }
            } else {
                // x region: 3-term bf16 split
                // pass 1: Ah * Bh
#pragma unroll
                for (int i = 0; i < 4; i++)
#pragma unroll
                    for (int p = 0; p < 2; p++) {
                        uint32_t b0[2] = {bh[p][0], bh[p][2]};
                        uint32_t b1[2] = {bh[p][1], bh[p][3]};
                        mma_16816(acc[i][p * 2 + 0], ah[i], b0);
                        mma_16816(acc[i][p * 2 + 1], ah[i], b1);
                    }
                // pass 2: Ah * Bl
                uint32_t bl[2][4];
#pragma unroll
                for (int p = 0; p < 2; p++)
                    ldmatrix_x4(bl[p][0], bl[p][1], bl[p][2], bl[p][3],
                                st + OFF_BL + b_off + p * 16 * ROWB + koff);
#pragma unroll
                for (int i = 0; i < 4; i++)
#pragma unroll
                    for (int p = 0; p < 2; p++) {
                        uint32_t b0[2] = {bl[p][0], bl[p][2]};
                        uint32_t b1[2] = {bl[p][1], bl[p][3]};
                        mma_16816(acc[i][p * 2 + 0], ah[i], b0);
                        mma_16816(acc[i][p * 2 + 1], ah[i], b1);
                    }
                // pass 3: Al * Bh
                uint32_t al[4][4];
#pragma unroll
                for (int i = 0; i < 4; i++)
                    ldmatrix_x4(al[i][0], al[i][1], al[i][2], al[i][3],
                                st + OFF_AL + a_off + i * 16 * ROWB + koff);
#pragma unroll
                for (int i = 0; i < 4; i++)
#pragma unroll
                    for (int p = 0; p < 2; p++) {
                        uint32_t b0[2] = {bh[p][0], bh[p][2]};
                        uint32_t b1[2] = {bh[p][1], bh[p][3]};
                        mma_16816(acc[i][p * 2 + 0], al[i], b0);
                        mma_16816(acc[i][p * 2 + 1], al[i], b1);
                    }
            }
        }
        __syncthreads();
        if (c + 2 < NCH) load_stage(st, (c + 2) * BK, (c + 2) < NXCH, pAh, pAl, pBh, pBl);
        CP_COMMIT();   // empty group when no loads -> wait count stays exact
    }

    // epilogue: split fp32 accumulators to bf16 hi/lo and store
    __nv_bfloat16* CH = g_qkvH + (size_t)which * NTOK * EMB;
    __nv_bfloat16* CL = g_qkvL + (size_t)which * NTOK * EMB;
    int mbase = row0 + wm * 64 + (lane >> 2);
    int nbase = col0 + wn * 32 + (lane & 3) * 2;
#pragma unroll
    for (int i = 0; i < 4; i++) {
#pragma unroll
        for (int j = 0; j < 4; j++) {
            size_t o0 = (size_t)(mbase + i * 16) * EMB + nbase + j * 8;
            size_t o1 = o0 + (size_t)8 * EMB;
            __nv_bfloat162 h2, l2;
            split_bf16(acc[i][j][0], h2.x, l2.x);
            split_bf16(acc[i][j][1], h2.y, l2.y);
            *(uint32_t*)(CH + o0) = *(uint32_t*)&h2;
            *(uint32_t*)(CL + o0) = *(uint32_t*)&l2;
            split_bf16(acc[i][j][2], h2.x, l2.x);
            split_bf16(acc[i][j][3], h2.y, l2.y);
            *(uint32_t*)(CH + o1) = *(uint32_t*)&h2;
            *(uint32_t*)(CL + o1) = *(uint32_t*)&l2;
        }
    }
}

// ---------------------------------------------------------------------------
// Kernel 4: scores via mma, 3-term split. CTA = (bh, 128q, 128k), one-shot.
// ---------------------------------------------------------------------------
#define QK_ROWB 144
#define QK_TILE (128 * QK_ROWB)
#define QK_QH 0
#define QK_QL QK_TILE
#define QK_KH (2 * QK_TILE)
#define QK_KL (3 * QK_TILE)
#define QK_SMEM (4 * QK_TILE)            // 73728

__global__ __launch_bounds__(256, 2) void qk_mma(float* __restrict__ S) {
    extern __shared__ char smem[];
    uint32_t sb = smem_to_u32(smem);
    int t = threadIdx.x;
    int lane = t & 31;
    int w = t >> 5;
    int wm = w >> 1;
    int wn = w & 1;

    int bh = blockIdx.z;
    int b = bh >> 4, h = bh & 15;
    int q0 = blockIdx.y * 128;
    int k0 = blockIdx.x * 128;

    const __nv_bfloat16* QH = g_qkvH + ((size_t)(b * SEQ + q0)) * EMB + h * HDIM;
    const __nv_bfloat16* QL = g_qkvL + ((size_t)(b * SEQ + q0)) * EMB + h * HDIM;
    const __nv_bfloat16* KH = g_qkvH + (size_t)NTOK * EMB + ((size_t)(b * SEQ + k0)) * EMB + h * HDIM;
    const __nv_bfloat16* KL = g_qkvL + (size_t)NTOK * EMB + ((size_t)(b * SEQ + k0)) * EMB + h * HDIM;

    {
        const __nv_bfloat16* srcs[4] = {QH, QL, KH, KL};
        uint32_t dsts[4] = {sb + QK_QH, sb + QK_QL, sb + QK_KH, sb + QK_KL};
#pragma unroll
        for (int j = 0; j < 16; j++) {
            int q = j * 256 + t;
            int op = q >> 10;
            int r = (q >> 3) & 127;
            int c = q & 7;
            cp_async16(dsts[op] + r * QK_ROWB + c * 16,
                       srcs[op] + (size_t)r * EMB + c * 8);
        }
    }
    CP_COMMIT();
    CP_WAIT0();
    __syncthreads();

    float acc[2][8][4];
#pragma unroll
    for (int i = 0; i < 2; i++)
#pragma unroll
        for (int j = 0; j < 8; j++)
#pragma unroll
            for (int q = 0; q < 4; q++) acc[i][j][q] = 0.0f;

    int lr = lane & 15;
    int lh = lane >> 4;
    uint32_t a_off = (uint32_t)((wm * 32 + lr) * QK_ROWB + lh * 16);
    uint32_t b_off = (uint32_t)((wn * 64 + lr) * QK_ROWB + lh * 16);

#pragma unroll
    for (int ks = 0; ks < 4; ks++) {
        uint32_t koff = ks * 32;
        uint32_t ah[2][4], al[2][4];
#pragma unroll
        for (int mi = 0; mi < 2; mi++) {
            ldmatrix_x4(ah[mi][0], ah[mi][1], ah[mi][2], ah[mi][3],
                        sb + QK_QH + a_off + mi * 16 * QK_ROWB + koff);
            ldmatrix_x4(al[mi][0], al[mi][1], al[mi][2], al[mi][3],
                        sb + QK_QL + a_off + mi * 16 * QK_ROWB + koff);
        }
#pragma unroll
        for (int p = 0; p < 4; p++) {
            uint32_t kh[4], kl[4];
            ldmatrix_x4(kh[0], kh[1], kh[2], kh[3],
                        sb + QK_KH + b_off + p * 16 * QK_ROWB + koff);
            ldmatrix_x4(kl[0], kl[1], kl[2], kl[3],
                        sb + QK_KL + b_off + p * 16 * QK_ROWB + koff);
            uint32_t b0h[2] = {kh[0], kh[2]};
            uint32_t b1h[2] = {kh[1], kh[3]};
            uint32_t b0l[2] = {kl[0], kl[2]};
            uint32_t b1l[2] = {kl[1], kl[3]};
#pragma unroll
            for (int mi = 0; mi < 2; mi++) {
                mma_16816(acc[mi][p * 2 + 0], ah[mi], b0h);
                mma_16816(acc[mi][p * 2 + 1], ah[mi], b1h);
            }
#pragma unroll
            for (int mi = 0; mi < 2; mi++) {
                mma_16816(acc[mi][p * 2 + 0], ah[mi], b0l);
                mma_16816(acc[mi][p * 2 + 1], ah[mi], b1l);
            }
#pragma unroll
            for (int mi = 0; mi < 2; mi++) {
                mma_16816(acc[mi][p * 2 + 0], al[mi], b0h);
                mma_16816(acc[mi][p * 2 + 1], al[mi], b1h);
            }
        }
    }

    float* Sb = S + (size_t)bh * SEQ * SEQ;
    const float scale = 0.125f;
#pragma unroll
    for (int mi = 0; mi < 2; mi++) {
        int r0 = q0 + wm * 32 + mi * 16 + (lane >> 2);
#pragma unroll
        for (int n = 0; n < 8; n++) {
            int col = k0 + wn * 64 + n * 8 + (lane & 3) * 2;
            *(float2*)(Sb + (size_t)r0 * SEQ + col) =
                make_float2(acc[mi][n][0] * scale, acc[mi][n][1] * scale);
            *(float2*)(Sb + (size_t)(r0 + 8) * SEQ + col) =
                make_float2(acc[mi][n][2] * scale, acc[mi][n][3] * scale);
        }
    }
}

// ---------------------------------------------------------------------------
// Kernel 5: in-place row softmax (one CTA per row of length SEQ)
// ---------------------------------------------------------------------------
__global__ __launch_bounds__(256) void softmax_kernel(float* __restrict__ W) {
    float* p = W + (size_t)blockIdx.x * SEQ;
    int t = threadIdx.x;
    float4 a = ((float4*)p)[t];
    float4 b = ((float4*)p)[t + 256];

    float m = fmaxf(fmaxf(fmaxf(a.x, a.y), fmaxf(a.z, a.w)),
                    fmaxf(fmaxf(b.x, b.y), fmaxf(b.z, b.w)));
#pragma unroll
    for (int o = 16; o > 0; o >>= 1) m = fmaxf(m, __shfl_xor_sync(0xffffffffu, m, o));

    __shared__ float red_max[8];
    __shared__ float red_sum[8];
    if ((t & 31) == 0) red_max[t >> 5] = m;
    __syncthreads();
    if (t < 32) {
        float v = (t < 8) ? red_max[t] : -3.402823466e38f;
#pragma unroll
        for (int o = 4; o > 0; o >>= 1) v = fmaxf(v, __shfl_xor_sync(0xffffffffu, v, o));
        if (t == 0) red_max[0] = v;
    }
    __syncthreads();
    m = red_max[0];

    a.x = __expf(a.x - m); a.y = __expf(a.y - m); a.z = __expf(a.z - m); a.w = __expf(a.w - m);
    b.x = __expf(b.x - m); b.y = __expf(b.y - m); b.z = __expf(b.z - m); b.w = __expf(b.w - m);
    float s = a.x + a.y + a.z + a.w + b.x + b.y + b.z + b.w;
#pragma unroll
    for (int o = 16; o > 0; o >>= 1) s += __shfl_xor_sync(0xffffffffu, s, o);
    if ((t & 31) == 0) red_sum[t >> 5] = s;
    __syncthreads();
    if (t < 32) {
        float v = (t < 8) ? red_sum[t] : 0.0f;
#pragma unroll
        for (int o = 4; o > 0; o >>= 1) v += __shfl_xor_sync(0xffffffffu, v, o);
        if (t == 0) red_sum[0] = v;
    }
    __syncthreads();
    float inv = 1.0f / red_sum[0];

    a.x *= inv; a.y *= inv; a.z *= inv; a.w *= inv;
    b.x *= inv; b.y *= inv; b.z *= inv; b.w *= inv;
    ((float4*)p)[t] = a;
    ((float4*)p)[t + 256] = b;
}

// ---------------------------------------------------------------------------
// Kernel 6: O = P @ V via mma, 3-term split (PhVh + PhVl + PlVh).
// ---------------------------------------------------------------------------
#define PV_PROWB 272
#define PV_VROWB 144
#define PV_PH 0
#define PV_PL (128 * PV_PROWB)
#define PV_VH (2 * 128 * PV_PROWB)
#define PV_VL (2 * 128 * PV_PROWB + 128 * PV_VROWB)
#define PV_SMEM (2 * 128 * PV_PROWB + 2 * 128 * PV_VROWB)  // 106496

__global__ __launch_bounds__(256, 2) void pv_mma(const float* __restrict__ P,
                                                 float* __restrict__ O) {
    extern __shared__ char smem[];
    uint32_t sb = smem_to_u32(smem);
    int t = threadIdx.x;
    int lane = t & 31;
    int w = t >> 5;
    int wm = w >> 1;
    int wn = w & 1;

    int bh = blockIdx.y;
    int b = bh >> 4, h = bh & 15;
    int q0 = blockIdx.x * 128;
    const float* Pb = P + (size_t)bh * SEQ * SEQ + (size_t)q0 * SEQ;
    const __nv_bfloat16* VH = g_qkvH + (size_t)2 * NTOK * EMB + (size_t)(b * SEQ) * EMB + h * HDIM;
    const __nv_bfloat16* VL = g_qkvL + (size_t)2 * NTOK * EMB + (size_t)(b * SEQ) * EMB + h * HDIM;

    float acc[2][4][4];
#pragma unroll
    for (int i = 0; i < 2; i++)
#pragma unroll
        for (int j = 0; j < 4; j++)
#pragma unroll
            for (int q = 0; q < 4; q++) acc[i][j][q] = 0.0f;

    int lr = lane & 15;
    int lh = lane >> 4;
    uint32_t a_off = (uint32_t)((wm * 32 + lr) * PV_PROWB + lh * 16);
    uint32_t vb_off = (uint32_t)(lr * PV_VROWB + (wn * 32 + lh * 8) * 2);

    for (int kc = 0; kc < SEQ / 128; kc++) {
        if (kc) __syncthreads();
#pragma unroll
        for (int j = 0; j < 8; j++) {
            int q = j * 256 + t;
            int op = q >> 10;
            int r = (q >> 3) & 127;
            int c = q & 7;
            const __nv_bfloat16* src = (op ? VL : VH) + (size_t)(kc * 128 + r) * EMB + c * 8;
            uint32_t dst = sb + (op ? PV_VL : PV_VH) + r * PV_VROWB + c * 16;
            cp_async16(dst, src);
        }
        CP_COMMIT();
#pragma unroll
        for (int j = 0; j < 16; j++) {
            int idx = j * 256 + t;
            int r = idx >> 5;
            int c4 = idx & 31;
            float4 v = *(const float4*)(Pb + (size_t)r * SEQ + kc * 128 + c4 * 4);
            __nv_bfloat162 h01, l01, h23, l23;
            split_bf16(v.x, h01.x, l01.x);
            split_bf16(v.y, h01.y, l01.y);
            split_bf16(v.z, h23.x, l23.x);
            split_bf16(v.w, h23.y, l23.y);
            uint32_t off = (uint32_t)(r * PV_PROWB + c4 * 8);
            *(uint2*)(smem + PV_PH + off) = make_uint2(*(uint32_t*)&h01, *(uint32_t*)&h23);
            *(uint2*)(smem + PV_PL + off) = make_uint2(*(uint32_t*)&l01, *(uint32_t*)&l23);
        }
        CP_WAIT0();
        __syncthreads();

#pragma unroll
        for (int ks = 0; ks < 8; ks++) {
            uint32_t koff = ks * 32;
            uint32_t ph[2][4], pl[2][4];
#pragma unroll
            for (int mi = 0; mi < 2; mi++) {
                ldmatrix_x4(ph[mi][0], ph[mi][1], ph[mi][2], ph[mi][3],
                            sb + PV_PH + a_off + mi * 16 * PV_PROWB + koff);
                ldmatrix_x4(pl[mi][0], pl[mi][1], pl[mi][2], pl[mi][3],
                            sb + PV_PL + a_off + mi * 16 * PV_PROWB + koff);
            }
            uint32_t vrow = (uint32_t)(ks * 16 * PV_VROWB);
            uint32_t vh[2][4], vl[2][4];
#pragma unroll
            for (int g = 0; g < 2; g++) {
                ldmatrix_x4_trans(vh[g][0], vh[g][1], vh[g][2], vh[g][3],
                                  sb + PV_VH + vb_off + vrow + g * 32);
                ldmatrix_x4_trans(vl[g][0], vl[g][1], vl[g][2], vl[g][3],
                                  sb + PV_VL + vb_off + vrow + g * 32);
            }
#pragma unroll
            for (int mi = 0; mi < 2; mi++)
#pragma unroll
                for (int g = 0; g < 2; g++) {
                    uint32_t b0[2] = {vh[g][0], vh[g][1]};
                    uint32_t b1[2] = {vh[g][2], vh[g][3]};
                    mma_16816(acc[mi][g * 2 + 0], ph[mi], b0);
                    mma_16816(acc[mi][g * 2 + 1], ph[mi], b1);
                }
#pragma unroll
            for (int mi = 0; mi < 2; mi++)
#pragma unroll
                for (int g = 0; g < 2; g++) {
                    uint32_t b0[2] = {vl[g][0], vl[g][1]};
                    uint32_t b1[2] = {vl[g][2], vl[g][3]};
                    mma_16816(acc[mi][g * 2 + 0], ph[mi], b0);
                    mma_16816(acc[mi][g * 2 + 1], ph[mi], b1);
                }
#pragma unroll
            for (int mi = 0; mi < 2; mi++)
#pragma unroll
                for (int g = 0; g < 2; g++) {
                    uint32_t b0[2] = {vh[g][0], vh[g][1]};
                    uint32_t b1[2] = {vh[g][2], vh[g][3]};
                    mma_16816(acc[mi][g * 2 + 0], pl[mi], b0);
                    mma_16816(acc[mi][g * 2 + 1], pl[mi], b1);
                }
        }
    }

    float* Ob = O + (size_t)(b * SEQ) * EMB + h * HDIM;
#pragma unroll
    for (int mi = 0; mi < 2; mi++) {
        int r0 = q0 + wm * 32 + mi * 16 + (lane >> 2);
#pragma unroll
        for (int n = 0; n < 4; n++) {
            int col = wn * 32 + n * 8 + (lane & 3) * 2;
            *(float2*)(Ob + (size_t)r0 * EMB + col) =
                make_float2(acc[mi][n][0], acc[mi][n][1]);
            *(float2*)(Ob + (size_t)(r0 + 8) * EMB + col) =
                make_float2(acc[mi][n][2], acc[mi][n][3]);
        }
    }
}

// ---------------------------------------------------------------------------
extern "C" void kernel_launch(void* const* d_in, const int* in_sizes, int n_in,
                              void* d_out, int out_size) {
    (void)in_sizes; (void)n_in; (void)out_size;
    float* out = (float*)d_out;                          // attn_output [B, L, E]
    float* attnw = out + (size_t)NTOK * EMB;             // attn_weights [B, H, L, L]

    Ptr3 X;
    X.p[0] = (const float*)d_in[0];
    X.p[1] = (const float*)d_in[1];
    X.p[2] = (const float*)d_in[2];
    PtrW Wp;
    for (int p = 0; p < 3; p++) {
        Wp.base[p]   = (const float*)d_in[3 + 3 * p];
        Wp.spline[p] = (const float*)d_in[4 + 3 * p];
        Wp.scaler[p] = (const float*)d_in[5 + 3 * p];
    }

    cudaFuncSetAttribute(gemm_kan_mma, cudaFuncAttributeMaxDynamicSharedMemorySize, GEMM_SMEM);
    cudaFuncSetAttribute(qk_mma, cudaFuncAttributeMaxDynamicSharedMemorySize, QK_SMEM);
    cudaFuncSetAttribute(pv_mma, cudaFuncAttributeMaxDynamicSharedMemorySize, PV_SMEM);

    phi_split_all<<<dim3((NTOK * EMB) / 256, 3), 256>>>(X);
    wprep_split_all<<<dim3((EMB * EMB) / 256, 3), 256>>>(Wp);
    gemm_kan_mma<<<dim3(EMB / BN, NTOK / BM, 3), GTHREADS, GEMM_SMEM>>>();
    qk_mma<<<dim3(SEQ / 128, SEQ / 128, BATCH * HEADS), 256, QK_SMEM>>>(attnw);
    softmax_kernel<<<BATCH * HEADS * SEQ, 256>>>(attnw);
    pv_mma<<<dim3(SEQ / 128, BATCH * HEADS), 256, PV_SMEM>>>(attnw, out);
}